// round 1
// baseline (speedup 1.0000x reference)
#include <cuda_runtime.h>
#include <math.h>

#define TM 32
#define NTHREADS 256
#define OBS_LD 52
#define ENC_LD 580
#define H_LD 260
#define T_LD 33

__device__ __forceinline__ float lrelu(float x) { return fmaxf(x, 0.01f * x); }

// ---------------------------------------------------------------------------
// layer1: [32 rows] x [K -> 32] + bias, lrelu. Output transposed: s_t[o][row].
// lane = row (conflict-free t writes), warp owns 4 output cols (uniform W reads).
// ---------------------------------------------------------------------------
template <int K>
__device__ __forceinline__ void layer1(const float* __restrict__ s_obs, int in_off,
                                       const float* __restrict__ W1,
                                       const float* __restrict__ b1,
                                       float* __restrict__ s_t, int tid) {
    const int row = tid & 31;
    const int o0 = (tid >> 5) * 4;
    const float* x = s_obs + row * OBS_LD + in_off;
    float4 b = __ldg((const float4*)(b1 + o0));
    float a0 = b.x, a1 = b.y, a2 = b.z, a3 = b.w;
#pragma unroll
    for (int k = 0; k < K; ++k) {
        float xv = x[k];
        float4 w = __ldg((const float4*)(W1 + k * 32 + o0));
        a0 = fmaf(xv, w.x, a0);
        a1 = fmaf(xv, w.y, a1);
        a2 = fmaf(xv, w.z, a2);
        a3 = fmaf(xv, w.w, a3);
    }
    s_t[(o0 + 0) * T_LD + row] = lrelu(a0);
    s_t[(o0 + 1) * T_LD + row] = lrelu(a1);
    s_t[(o0 + 2) * T_LD + row] = lrelu(a2);
    s_t[(o0 + 3) * T_LD + row] = lrelu(a3);
}

// ---------------------------------------------------------------------------
// layer2: [32 rows] x [32 -> N] + bias, lrelu, store or accumulate into enc.
// lane = row (conflict-free t reads); each warp owns distinct 8-col chunks so
// the CTA reads W2 exactly once (warp-uniform broadcast LDG).
// ---------------------------------------------------------------------------
__device__ __forceinline__ void layer2(const float* __restrict__ s_t,
                                       const float* __restrict__ W2,
                                       const float* __restrict__ b2,
                                       float* __restrict__ s_enc, int out_off, int N,
                                       bool add, int tid) {
    const int row = tid & 31;
    const int warp = tid >> 5;
    for (int c0 = warp * 8; c0 < N; c0 += 64) {
        float4 b0 = __ldg((const float4*)(b2 + c0));
        float4 b1v = __ldg((const float4*)(b2 + c0 + 4));
        float acc[8] = {b0.x, b0.y, b0.z, b0.w, b1v.x, b1v.y, b1v.z, b1v.w};
#pragma unroll 4
        for (int k = 0; k < 32; ++k) {
            float a = s_t[k * T_LD + row];
            float4 w0 = __ldg((const float4*)(W2 + k * N + c0));
            float4 w1 = __ldg((const float4*)(W2 + k * N + c0 + 4));
            acc[0] = fmaf(a, w0.x, acc[0]);
            acc[1] = fmaf(a, w0.y, acc[1]);
            acc[2] = fmaf(a, w0.z, acc[2]);
            acc[3] = fmaf(a, w0.w, acc[3]);
            acc[4] = fmaf(a, w1.x, acc[4]);
            acc[5] = fmaf(a, w1.y, acc[5]);
            acc[6] = fmaf(a, w1.z, acc[6]);
            acc[7] = fmaf(a, w1.w, acc[7]);
        }
        float* e = s_enc + row * ENC_LD + out_off + c0;
#pragma unroll
        for (int j = 0; j < 8; ++j) {
            float v = lrelu(acc[j]);
            e[j] = add ? (e[j] + v) : v;
        }
    }
}

// ---------------------------------------------------------------------------
// gemm32x256: sOut[32][256] = lrelu(sA[32][K] * Wg[K][256] + bg).
// Weights double-buffered through SMEM (sBuf: 2 * 8 * H_LD floats) so each
// CTA reads W from L2 exactly once. Thread micro-tile 4 rows x 8 cols;
// a-operands are warp-broadcast LDS, w-operands conflict-free LDS.128.
// sOut may alias sBuf (writes happen only after the final barrier).
// ---------------------------------------------------------------------------
__device__ void gemm32x256(const float* __restrict__ sA, int lda, int K,
                           const float* __restrict__ Wg, const float* __restrict__ bg,
                           float* __restrict__ sBuf, float* __restrict__ sOut, int ldo,
                           int tid) {
    const int r0 = (tid >> 5) * 4;
    const int c0 = (tid & 31) * 8;
    const int skl = tid >> 5;          // staged k-row within chunk
    const int sc = (tid & 31) * 8;     // staged col start

    float acc[4][8];
#pragma unroll
    for (int i = 0; i < 4; ++i)
#pragma unroll
        for (int j = 0; j < 8; ++j) acc[i][j] = 0.f;

    const int NC = K >> 3;  // chunks of 8 k-rows

    float4 p0 = __ldg((const float4*)(Wg + skl * 256 + sc));
    float4 p1 = __ldg((const float4*)(Wg + skl * 256 + sc + 4));
    {
        float* dst = sBuf + skl * H_LD + sc;
        *((float4*)dst) = p0;
        *((float4*)(dst + 4)) = p1;
    }
    __syncthreads();

    for (int kc = 0; kc < NC; ++kc) {
        if (kc + 1 < NC) {
            const float* src = Wg + ((kc + 1) * 8 + skl) * 256 + sc;
            p0 = __ldg((const float4*)src);
            p1 = __ldg((const float4*)(src + 4));
        }
        const float* bufc = sBuf + (kc & 1) * (8 * H_LD);
        float a[4][8];
#pragma unroll
        for (int i = 0; i < 4; ++i) {
            const float* ar = sA + (r0 + i) * lda + kc * 8;
            float4 x = *((const float4*)ar);
            float4 y = *((const float4*)(ar + 4));
            a[i][0] = x.x; a[i][1] = x.y; a[i][2] = x.z; a[i][3] = x.w;
            a[i][4] = y.x; a[i][5] = y.y; a[i][6] = y.z; a[i][7] = y.w;
        }
#pragma unroll
        for (int kk = 0; kk < 8; ++kk) {
            const float* wr = bufc + kk * H_LD + c0;
            float4 w0 = *((const float4*)wr);
            float4 w1 = *((const float4*)(wr + 4));
            float w[8] = {w0.x, w0.y, w0.z, w0.w, w1.x, w1.y, w1.z, w1.w};
#pragma unroll
            for (int i = 0; i < 4; ++i)
#pragma unroll
                for (int j = 0; j < 8; ++j)
                    acc[i][j] = fmaf(a[i][kk], w[j], acc[i][j]);
        }
        __syncthreads();
        if (kc + 1 < NC) {
            float* dst = sBuf + ((kc + 1) & 1) * (8 * H_LD) + skl * H_LD + sc;
            *((float4*)dst) = p0;
            *((float4*)(dst + 4)) = p1;
            __syncthreads();
        }
    }

    float4 b0 = __ldg((const float4*)(bg + c0));
    float4 b1v = __ldg((const float4*)(bg + c0 + 4));
    float bb[8] = {b0.x, b0.y, b0.z, b0.w, b1v.x, b1v.y, b1v.z, b1v.w};
#pragma unroll
    for (int i = 0; i < 4; ++i)
#pragma unroll
        for (int j = 0; j < 8; ++j)
            sOut[(r0 + i) * ldo + c0 + j] = lrelu(acc[i][j] + bb[j]);
}

// ---------------------------------------------------------------------------
// Fused kernel: one CTA = 32 batch rows of one player, full network in SMEM.
// ---------------------------------------------------------------------------
__global__ void __launch_bounds__(NTHREADS, 2)
mlpac_kernel(const float* __restrict__ obs,
             const float* __restrict__ prop_W1, const float* __restrict__ prop_b1,
             const float* __restrict__ prop_W2, const float* __restrict__ prop_b2,
             const float* __restrict__ ext_W1, const float* __restrict__ ext_b1,
             const float* __restrict__ ext_W2, const float* __restrict__ ext_b2,
             const float* __restrict__ opp_W1, const float* __restrict__ opp_b1,
             const float* __restrict__ opp_W2, const float* __restrict__ opp_b2,
             const float* __restrict__ pi_W1, const float* __restrict__ pi_b1,
             const float* __restrict__ pi_W2, const float* __restrict__ pi_b2,
             const float* __restrict__ pi_W3, const float* __restrict__ pi_b3,
             float* __restrict__ out) {
    extern __shared__ float sm[];
    float* s_obs = sm;                    // 32*52  = 1664 floats
    float* s_enc = sm + TM * OBS_LD;      // 32*580 = 18560 floats
    float* s_h1 = s_enc + TM * ENC_LD;    // 32*260 = 8320 floats
    float* s_t = s_h1;                    // scratch alias (32*33 <= 8320)

    const int tid = threadIdx.x;
    const int p = blockIdx.y;
    const int row0 = blockIdx.x * TM;

    // Load obs tile [32][48] (rows strided by P*OBS=144 in global)
    for (int idx = tid; idx < TM * 12; idx += NTHREADS) {
        int r = idx / 12, c = (idx % 12) * 4;
        const float* src = obs + ((long)(row0 + r) * 3 + p) * 48 + c;
        *((float4*)(s_obs + r * OBS_LD + c)) = __ldg((const float4*)src);
    }
    __syncthreads();

    // ---- prop encoder: 9 subnets [2 -> 32 -> 64], writes enc[64n .. 64n+63]
    {
        const float* W1 = prop_W1 + p * 9 * 2 * 32;
        const float* B1 = prop_b1 + p * 9 * 32;
        const float* W2 = prop_W2 + p * 9 * 32 * 64;
        const float* B2 = prop_b2 + p * 9 * 64;
        for (int n = 0; n < 9; ++n) {
            layer1<2>(s_obs, 2 * n, W1 + n * 64, B1 + n * 32, s_t, tid);
            __syncthreads();
            layer2(s_t, W2 + n * 2048, B2 + n * 64, s_enc, 64 * n, 64, false, tid);
            __syncthreads();
        }
    }
    // ---- ext encoder: 2 subnets [6 -> 32 -> 288], adds into enc[288n ..]
    {
        const float* W1 = ext_W1 + p * 2 * 6 * 32;
        const float* B1 = ext_b1 + p * 2 * 32;
        const float* W2 = ext_W2 + p * 2 * 32 * 288;
        const float* B2 = ext_b2 + p * 2 * 288;
        for (int n = 0; n < 2; ++n) {
            layer1<6>(s_obs, 18 + 6 * n, W1 + n * 192, B1 + n * 32, s_t, tid);
            __syncthreads();
            layer2(s_t, W2 + n * 9216, B2 + n * 288, s_enc, 288 * n, 288, true, tid);
            __syncthreads();
        }
    }
    // ---- opp encoder: [18 -> 32 -> 576], adds into enc
    layer1<18>(s_obs, 30, opp_W1 + p * 18 * 32, opp_b1 + p * 32, s_t, tid);
    __syncthreads();
    layer2(s_t, opp_W2 + p * 32 * 576, opp_b2 + p * 576, s_enc, 0, 576, true, tid);
    __syncthreads();

    // ---- pi1: enc[32][576] x W1[576][256] -> h1 (buf + out both in s_h1)
    gemm32x256(s_enc, ENC_LD, 576, pi_W1 + p * 576 * 256, pi_b1 + p * 256,
               s_h1, s_h1, H_LD, tid);
    __syncthreads();
    // ---- pi2: h1 x W2[256][256] -> h2 into s_enc[0..], buf at s_enc+8320
    gemm32x256(s_h1, H_LD, 256, pi_W2 + p * 256 * 256, pi_b2 + p * 256,
               s_enc + TM * H_LD, s_enc, H_LD, tid);
    __syncthreads();

    // ---- pi3 + tanh: 3 outputs per row
    if (tid < 96) {
        int row = tid / 3, o = tid % 3;
        const float* h2 = s_enc + row * H_LD;
        const float* W3 = pi_W3 + p * 768;
        float acc = 0.f;
#pragma unroll 8
        for (int k = 0; k < 256; ++k)
            acc = fmaf(h2[k], __ldg(W3 + k * 3 + o), acc);
        acc += __ldg(pi_b3 + p * 3 + o);
        out[((long)(row0 + row) * 3 + p) * 3 + o] = tanhf(acc);
    }
}

extern "C" void kernel_launch(void* const* d_in, const int* in_sizes, int n_in,
                              void* d_out, int out_size) {
    const float* obs = (const float*)d_in[0];
    const float* prop_W1 = (const float*)d_in[1];
    const float* prop_b1 = (const float*)d_in[2];
    const float* prop_W2 = (const float*)d_in[3];
    const float* prop_b2 = (const float*)d_in[4];
    const float* ext_W1 = (const float*)d_in[5];
    const float* ext_b1 = (const float*)d_in[6];
    const float* ext_W2 = (const float*)d_in[7];
    const float* ext_b2 = (const float*)d_in[8];
    const float* opp_W1 = (const float*)d_in[9];
    const float* opp_b1 = (const float*)d_in[10];
    const float* opp_W2 = (const float*)d_in[11];
    const float* opp_b2 = (const float*)d_in[12];
    const float* pi_W1 = (const float*)d_in[13];
    const float* pi_b1 = (const float*)d_in[14];
    const float* pi_W2 = (const float*)d_in[15];
    const float* pi_b2 = (const float*)d_in[16];
    const float* pi_W3 = (const float*)d_in[17];
    const float* pi_b3 = (const float*)d_in[18];
    float* out = (float*)d_out;

    size_t smem = (size_t)(TM * OBS_LD + TM * ENC_LD + TM * H_LD) * sizeof(float);
    cudaFuncSetAttribute(mlpac_kernel, cudaFuncAttributeMaxDynamicSharedMemorySize,
                         (int)smem);
    dim3 grid(65536 / TM, 3, 1);
    mlpac_kernel<<<grid, NTHREADS, smem>>>(
        obs, prop_W1, prop_b1, prop_W2, prop_b2, ext_W1, ext_b1, ext_W2, ext_b2,
        opp_W1, opp_b1, opp_W2, opp_b2, pi_W1, pi_b1, pi_W2, pi_b2, pi_W3, pi_b3,
        out);
}

// round 2
// speedup vs baseline: 1.6356x; 1.6356x over previous
#include <cuda_runtime.h>
#include <math.h>

#define TM 64
#define NT 256
#define OBS_LD 52
#define ENC_LD 580
#define H_LD 260
#define T_LD 65

typedef unsigned long long u64;

__device__ __forceinline__ float lrelu(float x) { return fmaxf(x, 0.01f * x); }

__device__ __forceinline__ u64 pack2(float x) {
    u64 r;
    unsigned int b = __float_as_uint(x);
    asm("mov.b64 %0, {%1, %1};" : "=l"(r) : "r"(b));
    return r;
}
__device__ __forceinline__ void ffma2(u64& d, u64 a, u64 b) {
    asm("fma.rn.f32x2 %0, %1, %2, %3;" : "=l"(d) : "l"(a), "l"(b), "l"(d));
}
__device__ __forceinline__ float2 unpack2(u64 v) {
    unsigned int lo, hi;
    asm("mov.b64 {%0, %1}, %2;" : "=r"(lo), "=r"(hi) : "l"(v));
    return make_float2(__uint_as_float(lo), __uint_as_float(hi));
}

// ---------------------------------------------------------------------------
// layer1: [64 rows] x [K -> 32] + bias, lrelu. Output transposed s_t[toff+o][row].
// row = tid&63 (conflict-free t writes), 4 groups x 8 outputs (uniform W reads).
// ---------------------------------------------------------------------------
template <int K>
__device__ __forceinline__ void layer1(const float* __restrict__ s_obs, int in_off,
                                       const float* __restrict__ W1,
                                       const float* __restrict__ b1,
                                       float* __restrict__ s_t, int toff, int tid) {
    const int row = tid & 63;
    const int o0 = (tid >> 6) * 8;
    const float* x = s_obs + row * OBS_LD + in_off;
    float4 b0 = __ldg((const float4*)(b1 + o0));
    float4 b1v = __ldg((const float4*)(b1 + o0 + 4));
    float acc[8] = {b0.x, b0.y, b0.z, b0.w, b1v.x, b1v.y, b1v.z, b1v.w};
#pragma unroll
    for (int k = 0; k < K; ++k) {
        float xv = x[k];
        float4 w0 = __ldg((const float4*)(W1 + k * 32 + o0));
        float4 w1 = __ldg((const float4*)(W1 + k * 32 + o0 + 4));
        acc[0] = fmaf(xv, w0.x, acc[0]);
        acc[1] = fmaf(xv, w0.y, acc[1]);
        acc[2] = fmaf(xv, w0.z, acc[2]);
        acc[3] = fmaf(xv, w0.w, acc[3]);
        acc[4] = fmaf(xv, w1.x, acc[4]);
        acc[5] = fmaf(xv, w1.y, acc[5]);
        acc[6] = fmaf(xv, w1.z, acc[6]);
        acc[7] = fmaf(xv, w1.w, acc[7]);
    }
#pragma unroll
    for (int j = 0; j < 8; ++j)
        s_t[(toff + o0 + j) * T_LD + row] = lrelu(acc[j]);
}

// ---------------------------------------------------------------------------
// layer2: [64 rows] x [32 -> NV virtual cols] + bias, lrelu, store/add to enc.
// Virtual cols concatenate subnets of width SW (t rows: subnet s at s*32).
// Thread: rows {ra, ra+16, ra+32, ra+48} x 16 cols; 16 col groups. f32x2 math.
// W reads warp-uniform (g = tid>>4 uniform within warp). enc col = encbase+c0.
// ---------------------------------------------------------------------------
__device__ void layer2(const float* __restrict__ s_t,
                       const float* __restrict__ W2, const float* __restrict__ b2,
                       int SW, int NV, float* __restrict__ s_enc, int encbase,
                       bool add, int tid) {
    const int ra = tid & 15;
    const int g = tid >> 4;
    for (int c0 = g * 16; c0 < NV; c0 += 256) {
        const int s = c0 / SW;
        const int lc0 = c0 - s * SW;
        const float* W = W2 + s * 32 * SW + lc0;
        const float* tt = s_t + s * 32 * T_LD;

        u64 acc[4][8];
        {
            const float* bb = b2 + c0;
#pragma unroll
            for (int j = 0; j < 8; ++j) {
                u64 bp = ((const u64*)bb)[j];
#pragma unroll
                for (int m = 0; m < 4; ++m) acc[m][j] = bp;
            }
        }
#pragma unroll 2
        for (int k = 0; k < 32; ++k) {
            const float* wr = W + k * SW;
            ulonglong2 wa = __ldg((const ulonglong2*)(wr));
            ulonglong2 wb = __ldg((const ulonglong2*)(wr + 4));
            ulonglong2 wc = __ldg((const ulonglong2*)(wr + 8));
            ulonglong2 wd = __ldg((const ulonglong2*)(wr + 12));
            u64 w[8] = {wa.x, wa.y, wb.x, wb.y, wc.x, wc.y, wd.x, wd.y};
#pragma unroll
            for (int m = 0; m < 4; ++m) {
                u64 tp = pack2(tt[k * T_LD + ra + m * 16]);
#pragma unroll
                for (int j = 0; j < 8; ++j) ffma2(acc[m][j], tp, w[j]);
            }
        }
#pragma unroll
        for (int m = 0; m < 4; ++m) {
            float* e = s_enc + (ra + m * 16) * ENC_LD + encbase + c0;
            float v[16];
#pragma unroll
            for (int j = 0; j < 8; ++j) {
                float2 f = unpack2(acc[m][j]);
                v[2 * j] = lrelu(f.x);
                v[2 * j + 1] = lrelu(f.y);
            }
#pragma unroll
            for (int q = 0; q < 4; ++q) {
                float4 nv = make_float4(v[4 * q], v[4 * q + 1], v[4 * q + 2], v[4 * q + 3]);
                if (add) {
                    float4 old = *((float4*)(e + 4 * q));
                    nv.x += old.x; nv.y += old.y; nv.z += old.z; nv.w += old.w;
                }
                *((float4*)(e + 4 * q)) = nv;
            }
        }
    }
}

// ---------------------------------------------------------------------------
// gemm64x256: sOut[64][256] = lrelu(sA[64][K] * Wg[K][256] + bg).
// 8 warps, thread tile 8 rows x 8 cols (cols lane*4..+3 and 128+lane*4..+3).
// Weights double-buffered via SMEM (sBuf 2*2048 floats); A rows uniform LDS.128;
// w loads lane-contiguous LDS.128 (4 wavefronts). f32x2 accumulation.
// sOut may alias sBuf (written only after the final barrier).
// ---------------------------------------------------------------------------
__device__ void gemm64x256(const float* __restrict__ sA, int lda, int K,
                           const float* __restrict__ Wg, const float* __restrict__ bg,
                           float* __restrict__ sBuf, float* __restrict__ sOut, int ldo,
                           int tid) {
    const int warp = tid >> 5;
    const int lane = tid & 31;
    const int r0 = warp * 8;
    const int cA = lane * 4;
    const int cB = 128 + lane * 4;

    u64 acc[8][4];
#pragma unroll
    for (int i = 0; i < 8; ++i)
#pragma unroll
        for (int j = 0; j < 4; ++j) acc[i][j] = 0ULL;

    const int NC = K >> 3;

    float4 p0 = __ldg((const float4*)(Wg + warp * 256 + cA));
    float4 p1 = __ldg((const float4*)(Wg + warp * 256 + cB));
    *((float4*)(sBuf + warp * 256 + cA)) = p0;
    *((float4*)(sBuf + warp * 256 + cB)) = p1;
    __syncthreads();

    for (int kc = 0; kc < NC; ++kc) {
        if (kc + 1 < NC) {
            const float* src = Wg + ((kc + 1) * 8 + warp) * 256;
            p0 = __ldg((const float4*)(src + cA));
            p1 = __ldg((const float4*)(src + cB));
        }
        const float* bufc = sBuf + (kc & 1) * 2048;

        float a[8][8];
#pragma unroll
        for (int i = 0; i < 8; ++i) {
            const float* ar = sA + (r0 + i) * lda + kc * 8;
            float4 x = *((const float4*)ar);
            float4 y = *((const float4*)(ar + 4));
            a[i][0] = x.x; a[i][1] = x.y; a[i][2] = x.z; a[i][3] = x.w;
            a[i][4] = y.x; a[i][5] = y.y; a[i][6] = y.z; a[i][7] = y.w;
        }
#pragma unroll
        for (int kk = 0; kk < 8; ++kk) {
            const float* wr = bufc + kk * 256;
            ulonglong2 w01 = *((const ulonglong2*)(wr + cA));
            ulonglong2 w23 = *((const ulonglong2*)(wr + cB));
#pragma unroll
            for (int i = 0; i < 8; ++i) {
                u64 ap = pack2(a[i][kk]);
                ffma2(acc[i][0], ap, w01.x);
                ffma2(acc[i][1], ap, w01.y);
                ffma2(acc[i][2], ap, w23.x);
                ffma2(acc[i][3], ap, w23.y);
            }
        }
        __syncthreads();
        if (kc + 1 < NC) {
            float* dst = sBuf + ((kc + 1) & 1) * 2048 + warp * 256;
            *((float4*)(dst + cA)) = p0;
            *((float4*)(dst + cB)) = p1;
            __syncthreads();
        }
    }

    float4 bA = __ldg((const float4*)(bg + cA));
    float4 bB = __ldg((const float4*)(bg + cB));
#pragma unroll
    for (int i = 0; i < 8; ++i) {
        float2 f0 = unpack2(acc[i][0]);
        float2 f1 = unpack2(acc[i][1]);
        float2 f2 = unpack2(acc[i][2]);
        float2 f3 = unpack2(acc[i][3]);
        float4 oA = make_float4(lrelu(f0.x + bA.x), lrelu(f0.y + bA.y),
                                lrelu(f1.x + bA.z), lrelu(f1.y + bA.w));
        float4 oB = make_float4(lrelu(f2.x + bB.x), lrelu(f2.y + bB.y),
                                lrelu(f3.x + bB.z), lrelu(f3.y + bB.w));
        *((float4*)(sOut + (r0 + i) * ldo + cA)) = oA;
        *((float4*)(sOut + (r0 + i) * ldo + cB)) = oB;
    }
}

// ---------------------------------------------------------------------------
// Fused kernel: one CTA = 64 batch rows of one player, full network in SMEM.
// ---------------------------------------------------------------------------
__global__ void __launch_bounds__(NT, 1)
mlpac_kernel(const float* __restrict__ obs,
             const float* __restrict__ prop_W1, const float* __restrict__ prop_b1,
             const float* __restrict__ prop_W2, const float* __restrict__ prop_b2,
             const float* __restrict__ ext_W1, const float* __restrict__ ext_b1,
             const float* __restrict__ ext_W2, const float* __restrict__ ext_b2,
             const float* __restrict__ opp_W1, const float* __restrict__ opp_b1,
             const float* __restrict__ opp_W2, const float* __restrict__ opp_b2,
             const float* __restrict__ pi_W1, const float* __restrict__ pi_b1,
             const float* __restrict__ pi_W2, const float* __restrict__ pi_b2,
             const float* __restrict__ pi_W3, const float* __restrict__ pi_b3,
             float* __restrict__ out) {
    extern __shared__ float sm[];
    float* s_obs = sm;                       // 64*52  = 3328
    float* s_enc = sm + TM * OBS_LD;         // 64*580 = 37120
    float* s_h1 = s_enc + TM * ENC_LD;       // 64*260 = 16640
    float* s_t = s_h1;                       // encoder scratch alias (<=8320)

    const int tid = threadIdx.x;
    const int p = blockIdx.y;
    const int row0 = blockIdx.x * TM;

    // Load obs tile [64][48]
    for (int idx = tid; idx < TM * 12; idx += NT) {
        int r = idx / 12, c = (idx % 12) * 4;
        const float* src = obs + ((long)(row0 + r) * 3 + p) * 48 + c;
        *((float4*)(s_obs + r * OBS_LD + c)) = __ldg((const float4*)src);
    }
    __syncthreads();

    // ---- prop encoder: 9 subnets [2->32->64] in quads (4+4+1)
    {
        const float* W1 = prop_W1 + p * 9 * 64;
        const float* B1 = prop_b1 + p * 9 * 32;
        const float* W2 = prop_W2 + p * 9 * 2048;
        const float* B2 = prop_b2 + p * 576;
        for (int q = 0; q < 8; q += 4) {
#pragma unroll
            for (int n = 0; n < 4; ++n)
                layer1<2>(s_obs, 2 * (q + n), W1 + (q + n) * 64, B1 + (q + n) * 32,
                          s_t, n * 32, tid);
            __syncthreads();
            layer2(s_t, W2 + q * 2048, B2 + q * 64, 64, 256, s_enc, q * 64, false, tid);
            __syncthreads();
        }
        layer1<2>(s_obs, 16, W1 + 8 * 64, B1 + 8 * 32, s_t, 0, tid);
        __syncthreads();
        layer2(s_t, W2 + 8 * 2048, B2 + 512, 64, 64, s_enc, 512, false, tid);
        __syncthreads();
    }
    // ---- ext encoder: 2 subnets [6->32->288] as one pair
    {
        const float* W1 = ext_W1 + p * 2 * 192;
        const float* B1 = ext_b1 + p * 64;
        const float* W2 = ext_W2 + p * 2 * 9216;
        const float* B2 = ext_b2 + p * 576;
        layer1<6>(s_obs, 18, W1, B1, s_t, 0, tid);
        layer1<6>(s_obs, 24, W1 + 192, B1 + 32, s_t, 32, tid);
        __syncthreads();
        layer2(s_t, W2, B2, 288, 576, s_enc, 0, true, tid);
        __syncthreads();
    }
    // ---- opp encoder: [18->32->576]
    layer1<18>(s_obs, 30, opp_W1 + p * 576, opp_b1 + p * 32, s_t, 0, tid);
    __syncthreads();
    layer2(s_t, opp_W2 + p * 32 * 576, opp_b2 + p * 576, 576, 576, s_enc, 0, true, tid);
    __syncthreads();

    // ---- pi1: enc[64][576] x W1[576][256] -> h1 (buf aliases s_h1)
    gemm64x256(s_enc, ENC_LD, 576, pi_W1 + p * 576 * 256, pi_b1 + p * 256,
               s_h1, s_h1, H_LD, tid);
    __syncthreads();
    // ---- pi2: h1 x W2[256][256] -> h2 in s_enc[0..], buf at s_enc+20480
    gemm64x256(s_h1, H_LD, 256, pi_W2 + p * 256 * 256, pi_b2 + p * 256,
               s_enc + 20480, s_enc, H_LD, tid);

    // ---- stage W3/b3 into s_obs (dead), then pi3 + tanh
    for (int i = tid; i < 768; i += NT) s_obs[i] = __ldg(pi_W3 + p * 768 + i);
    if (tid < 3) s_obs[768 + tid] = __ldg(pi_b3 + p * 3 + tid);
    __syncthreads();

    if (tid < 192) {
        int row = tid / 3, o = tid - row * 3;
        const float* h2 = s_enc + row * H_LD;
        float acc = s_obs[768 + o];
#pragma unroll 8
        for (int k = 0; k < 256; ++k)
            acc = fmaf(h2[k], s_obs[k * 3 + o], acc);
        out[((long)(row0 + row) * 3 + p) * 3 + o] = tanhf(acc);
    }
}

extern "C" void kernel_launch(void* const* d_in, const int* in_sizes, int n_in,
                              void* d_out, int out_size) {
    const float* obs = (const float*)d_in[0];
    const float* prop_W1 = (const float*)d_in[1];
    const float* prop_b1 = (const float*)d_in[2];
    const float* prop_W2 = (const float*)d_in[3];
    const float* prop_b2 = (const float*)d_in[4];
    const float* ext_W1 = (const float*)d_in[5];
    const float* ext_b1 = (const float*)d_in[6];
    const float* ext_W2 = (const float*)d_in[7];
    const float* ext_b2 = (const float*)d_in[8];
    const float* opp_W1 = (const float*)d_in[9];
    const float* opp_b1 = (const float*)d_in[10];
    const float* opp_W2 = (const float*)d_in[11];
    const float* opp_b2 = (const float*)d_in[12];
    const float* pi_W1 = (const float*)d_in[13];
    const float* pi_b1 = (const float*)d_in[14];
    const float* pi_W2 = (const float*)d_in[15];
    const float* pi_b2 = (const float*)d_in[16];
    const float* pi_W3 = (const float*)d_in[17];
    const float* pi_b3 = (const float*)d_in[18];
    float* out = (float*)d_out;

    size_t smem = (size_t)(TM * OBS_LD + TM * ENC_LD + TM * H_LD) * sizeof(float);
    cudaFuncSetAttribute(mlpac_kernel, cudaFuncAttributeMaxDynamicSharedMemorySize,
                         (int)smem);
    dim3 grid(65536 / TM, 3, 1);
    mlpac_kernel<<<grid, NT, smem>>>(
        obs, prop_W1, prop_b1, prop_W2, prop_b2, ext_W1, ext_b1, ext_W2, ext_b2,
        opp_W1, opp_b1, opp_W2, opp_b2, pi_W1, pi_b1, pi_W2, pi_b2, pi_W3, pi_b3,
        out);
}

// round 3
// speedup vs baseline: 1.7088x; 1.0448x over previous
#include <cuda_runtime.h>
#include <math.h>

#define TM 64
#define NT 512
#define OBS_LD 52
#define ENC_LD 580
#define H_LD 260
#define T_LD 65

typedef unsigned long long u64;

__device__ __forceinline__ float lrelu(float x) { return fmaxf(x, 0.01f * x); }

__device__ __forceinline__ u64 pack2(float x) {
    u64 r;
    unsigned int b = __float_as_uint(x);
    asm("mov.b64 %0, {%1, %1};" : "=l"(r) : "r"(b));
    return r;
}
__device__ __forceinline__ void ffma2(u64& d, u64 a, u64 b) {
    asm("fma.rn.f32x2 %0, %1, %2, %3;" : "=l"(d) : "l"(a), "l"(b), "l"(d));
}
__device__ __forceinline__ float2 unpack2(u64 v) {
    unsigned int lo, hi;
    asm("mov.b64 {%0, %1}, %2;" : "=r"(lo), "=r"(hi) : "l"(v));
    return make_float2(__uint_as_float(lo), __uint_as_float(hi));
}

// ---------------------------------------------------------------------------
// layer1: [64 rows] x [K -> 32] + bias, lrelu. Output transposed s_t[toff+o][row].
// 512 thr: row = tid&63, 8 groups x 4 outputs (uniform W reads per group).
// ---------------------------------------------------------------------------
template <int K>
__device__ __forceinline__ void layer1(const float* __restrict__ s_obs, int in_off,
                                       const float* __restrict__ W1,
                                       const float* __restrict__ b1,
                                       float* __restrict__ s_t, int toff, int tid) {
    const int row = tid & 63;
    const int o0 = (tid >> 6) * 4;
    const float* x = s_obs + row * OBS_LD + in_off;
    float4 b = __ldg((const float4*)(b1 + o0));
    float acc[4] = {b.x, b.y, b.z, b.w};
#pragma unroll
    for (int k = 0; k < K; ++k) {
        float xv = x[k];
        float4 w = __ldg((const float4*)(W1 + k * 32 + o0));
        acc[0] = fmaf(xv, w.x, acc[0]);
        acc[1] = fmaf(xv, w.y, acc[1]);
        acc[2] = fmaf(xv, w.z, acc[2]);
        acc[3] = fmaf(xv, w.w, acc[3]);
    }
#pragma unroll
    for (int j = 0; j < 4; ++j)
        s_t[(toff + o0 + j) * T_LD + row] = lrelu(acc[j]);
}

// ---------------------------------------------------------------------------
// layer2: [64 rows] x [32 -> NV virtual cols] + bias, lrelu, store/add to enc.
// Virtual cols concatenate subnets of width SW (t rows: subnet s at s*32).
// 512 thr: 32 groups x 16 cols per sweep; thread rows {ra, +16, +32, +48}.
// f32x2 math; W reads uniform within each 16-thread group.
// ---------------------------------------------------------------------------
__device__ void layer2(const float* __restrict__ s_t,
                       const float* __restrict__ W2, const float* __restrict__ b2,
                       int SW, int NV, float* __restrict__ s_enc, int encbase,
                       bool add, int tid) {
    const int ra = tid & 15;
    const int g = tid >> 4;
    for (int c0 = g * 16; c0 < NV; c0 += 512) {
        const int s = c0 / SW;
        const int lc0 = c0 - s * SW;
        const float* W = W2 + s * 32 * SW + lc0;
        const float* tt = s_t + s * 32 * T_LD;

        u64 acc[4][8];
        {
            const float* bb = b2 + c0;
#pragma unroll
            for (int j = 0; j < 8; ++j) {
                u64 bp = ((const u64*)bb)[j];
#pragma unroll
                for (int m = 0; m < 4; ++m) acc[m][j] = bp;
            }
        }
#pragma unroll 2
        for (int k = 0; k < 32; ++k) {
            const float* wr = W + k * SW;
            ulonglong2 wa = __ldg((const ulonglong2*)(wr));
            ulonglong2 wb = __ldg((const ulonglong2*)(wr + 4));
            ulonglong2 wc = __ldg((const ulonglong2*)(wr + 8));
            ulonglong2 wd = __ldg((const ulonglong2*)(wr + 12));
            u64 w[8] = {wa.x, wa.y, wb.x, wb.y, wc.x, wc.y, wd.x, wd.y};
#pragma unroll
            for (int m = 0; m < 4; ++m) {
                u64 tp = pack2(tt[k * T_LD + ra + m * 16]);
#pragma unroll
                for (int j = 0; j < 8; ++j) ffma2(acc[m][j], tp, w[j]);
            }
        }
#pragma unroll
        for (int m = 0; m < 4; ++m) {
            float* e = s_enc + (ra + m * 16) * ENC_LD + encbase + c0;
            float v[16];
#pragma unroll
            for (int j = 0; j < 8; ++j) {
                float2 f = unpack2(acc[m][j]);
                v[2 * j] = lrelu(f.x);
                v[2 * j + 1] = lrelu(f.y);
            }
#pragma unroll
            for (int q = 0; q < 4; ++q) {
                float4 nv = make_float4(v[4 * q], v[4 * q + 1], v[4 * q + 2], v[4 * q + 3]);
                if (add) {
                    float4 old = *((float4*)(e + 4 * q));
                    nv.x += old.x; nv.y += old.y; nv.z += old.z; nv.w += old.w;
                }
                *((float4*)(e + 4 * q)) = nv;
            }
        }
    }
}

// ---------------------------------------------------------------------------
// gemm64x256: sOut[64][256] = lrelu(sA[64][K] * Wg[K][256] + bg).
// 16 warps, thread tile 4 rows x 8 cols (cols lane*4..+3 and 128+lane*4..+3).
// Chunk = 16 k-rows; each warp stages one row (lane covers 8 floats).
// Double-buffered with ONE __syncthreads per chunk. f32x2 accumulation.
// sOut may alias sBuf (written only after the loop's final barrier).
// ---------------------------------------------------------------------------
__device__ void gemm64x256(const float* __restrict__ sA, int lda, int K,
                           const float* __restrict__ Wg, const float* __restrict__ bg,
                           float* __restrict__ sBuf, float* __restrict__ sOut, int ldo,
                           int tid) {
    const int warp = tid >> 5;
    const int lane = tid & 31;
    const int r0 = warp * 4;
    const int cA = lane * 4;
    const int cB = 128 + lane * 4;
    const int sof = warp * 256 + lane * 8;

    u64 acc[4][4];
#pragma unroll
    for (int i = 0; i < 4; ++i)
#pragma unroll
        for (int j = 0; j < 4; ++j) acc[i][j] = 0ULL;

    const int NC = K >> 4;

    float4 p0 = __ldg((const float4*)(Wg + sof));
    float4 p1 = __ldg((const float4*)(Wg + sof + 4));
    *((float4*)(sBuf + sof)) = p0;
    *((float4*)(sBuf + sof + 4)) = p1;
    __syncthreads();

    for (int kc = 0; kc < NC; ++kc) {
        if (kc + 1 < NC) {
            const float* src = Wg + (kc + 1) * 4096 + sof;
            p0 = __ldg((const float4*)src);
            p1 = __ldg((const float4*)(src + 4));
        }
        const float* bufc = sBuf + (kc & 1) * 4096;
#pragma unroll
        for (int h = 0; h < 2; ++h) {
            float a[4][8];
#pragma unroll
            for (int i = 0; i < 4; ++i) {
                const float* ar = sA + (r0 + i) * lda + kc * 16 + h * 8;
                float4 x = *((const float4*)ar);
                float4 y = *((const float4*)(ar + 4));
                a[i][0] = x.x; a[i][1] = x.y; a[i][2] = x.z; a[i][3] = x.w;
                a[i][4] = y.x; a[i][5] = y.y; a[i][6] = y.z; a[i][7] = y.w;
            }
#pragma unroll
            for (int kk = 0; kk < 8; ++kk) {
                const float* wr = bufc + (h * 8 + kk) * 256;
                ulonglong2 w01 = *((const ulonglong2*)(wr + cA));
                ulonglong2 w23 = *((const ulonglong2*)(wr + cB));
#pragma unroll
                for (int i = 0; i < 4; ++i) {
                    u64 ap = pack2(a[i][kk]);
                    ffma2(acc[i][0], ap, w01.x);
                    ffma2(acc[i][1], ap, w01.y);
                    ffma2(acc[i][2], ap, w23.x);
                    ffma2(acc[i][3], ap, w23.y);
                }
            }
        }
        if (kc + 1 < NC) {
            float* dst = sBuf + ((kc + 1) & 1) * 4096 + sof;
            *((float4*)dst) = p0;
            *((float4*)(dst + 4)) = p1;
        }
        __syncthreads();
    }

    float4 bA = __ldg((const float4*)(bg + cA));
    float4 bB = __ldg((const float4*)(bg + cB));
#pragma unroll
    for (int i = 0; i < 4; ++i) {
        float2 f0 = unpack2(acc[i][0]);
        float2 f1 = unpack2(acc[i][1]);
        float2 f2 = unpack2(acc[i][2]);
        float2 f3 = unpack2(acc[i][3]);
        float4 oA = make_float4(lrelu(f0.x + bA.x), lrelu(f0.y + bA.y),
                                lrelu(f1.x + bA.z), lrelu(f1.y + bA.w));
        float4 oB = make_float4(lrelu(f2.x + bB.x), lrelu(f2.y + bB.y),
                                lrelu(f3.x + bB.z), lrelu(f3.y + bB.w));
        *((float4*)(sOut + (r0 + i) * ldo + cA)) = oA;
        *((float4*)(sOut + (r0 + i) * ldo + cB)) = oB;
    }
}

// ---------------------------------------------------------------------------
// Fused kernel: one CTA = 64 batch rows of one player, full network in SMEM.
// ---------------------------------------------------------------------------
__global__ void __launch_bounds__(NT, 1)
mlpac_kernel(const float* __restrict__ obs,
             const float* __restrict__ prop_W1, const float* __restrict__ prop_b1,
             const float* __restrict__ prop_W2, const float* __restrict__ prop_b2,
             const float* __restrict__ ext_W1, const float* __restrict__ ext_b1,
             const float* __restrict__ ext_W2, const float* __restrict__ ext_b2,
             const float* __restrict__ opp_W1, const float* __restrict__ opp_b1,
             const float* __restrict__ opp_W2, const float* __restrict__ opp_b2,
             const float* __restrict__ pi_W1, const float* __restrict__ pi_b1,
             const float* __restrict__ pi_W2, const float* __restrict__ pi_b2,
             const float* __restrict__ pi_W3, const float* __restrict__ pi_b3,
             float* __restrict__ out) {
    extern __shared__ float sm[];
    float* s_obs = sm;                       // 64*52  = 3328
    float* s_enc = sm + TM * OBS_LD;         // 64*580 = 37120
    float* s_h1 = s_enc + TM * ENC_LD;       // 64*260 = 16640
    float* s_t = s_h1;                       // encoder scratch alias (<=16640)

    const int tid = threadIdx.x;
    const int p = blockIdx.y;
    const int row0 = blockIdx.x * TM;

    // Load obs tile [64][48]
    for (int idx = tid; idx < TM * 12; idx += NT) {
        int r = idx / 12, c = (idx % 12) * 4;
        const float* src = obs + ((long)(row0 + r) * 3 + p) * 48 + c;
        *((float4*)(s_obs + r * OBS_LD + c)) = __ldg((const float4*)src);
    }
    __syncthreads();

    // ---- prop encoder: 9 subnets [2->32->64]; 8 at once, then 1
    {
        const float* W1 = prop_W1 + p * 9 * 64;
        const float* B1 = prop_b1 + p * 9 * 32;
        const float* W2 = prop_W2 + p * 9 * 2048;
        const float* B2 = prop_b2 + p * 576;
#pragma unroll
        for (int n = 0; n < 8; ++n)
            layer1<2>(s_obs, 2 * n, W1 + n * 64, B1 + n * 32, s_t, n * 32, tid);
        __syncthreads();
        layer2(s_t, W2, B2, 64, 512, s_enc, 0, false, tid);
        __syncthreads();
        layer1<2>(s_obs, 16, W1 + 8 * 64, B1 + 8 * 32, s_t, 0, tid);
        __syncthreads();
        layer2(s_t, W2 + 8 * 2048, B2 + 512, 64, 64, s_enc, 512, false, tid);
        __syncthreads();
    }
    // ---- ext encoder: 2 subnets [6->32->288] as one pair
    {
        const float* W1 = ext_W1 + p * 2 * 192;
        const float* B1 = ext_b1 + p * 64;
        const float* W2 = ext_W2 + p * 2 * 9216;
        const float* B2 = ext_b2 + p * 576;
        layer1<6>(s_obs, 18, W1, B1, s_t, 0, tid);
        layer1<6>(s_obs, 24, W1 + 192, B1 + 32, s_t, 32, tid);
        __syncthreads();
        layer2(s_t, W2, B2, 288, 576, s_enc, 0, true, tid);
        __syncthreads();
    }
    // ---- opp encoder: [18->32->576]
    layer1<18>(s_obs, 30, opp_W1 + p * 576, opp_b1 + p * 32, s_t, 0, tid);
    __syncthreads();
    layer2(s_t, opp_W2 + p * 32 * 576, opp_b2 + p * 576, 576, 576, s_enc, 0, true, tid);
    __syncthreads();

    // ---- pi1: enc[64][576] x W1[576][256] -> h1 (buf aliases s_h1)
    gemm64x256(s_enc, ENC_LD, 576, pi_W1 + p * 576 * 256, pi_b1 + p * 256,
               s_h1, s_h1, H_LD, tid);
    __syncthreads();
    // ---- pi2: h1 x W2[256][256] -> h2 in s_enc[0..], buf at s_enc+20480
    gemm64x256(s_h1, H_LD, 256, pi_W2 + p * 256 * 256, pi_b2 + p * 256,
               s_enc + 20480, s_enc, H_LD, tid);

    // ---- stage W3/b3 into s_obs (dead), then pi3 + tanh
    for (int i = tid; i < 768; i += NT) s_obs[i] = __ldg(pi_W3 + p * 768 + i);
    if (tid < 3) s_obs[768 + tid] = __ldg(pi_b3 + p * 3 + tid);
    __syncthreads();

    if (tid < 192) {
        int row = tid / 3, o = tid - row * 3;
        const float* h2 = s_enc + row * H_LD;
        float acc = s_obs[768 + o];
#pragma unroll 8
        for (int k = 0; k < 256; ++k)
            acc = fmaf(h2[k], s_obs[k * 3 + o], acc);
        out[((long)(row0 + row) * 3 + p) * 3 + o] = tanhf(acc);
    }
}

extern "C" void kernel_launch(void* const* d_in, const int* in_sizes, int n_in,
                              void* d_out, int out_size) {
    const float* obs = (const float*)d_in[0];
    const float* prop_W1 = (const float*)d_in[1];
    const float* prop_b1 = (const float*)d_in[2];
    const float* prop_W2 = (const float*)d_in[3];
    const float* prop_b2 = (const float*)d_in[4];
    const float* ext_W1 = (const float*)d_in[5];
    const float* ext_b1 = (const float*)d_in[6];
    const float* ext_W2 = (const float*)d_in[7];
    const float* ext_b2 = (const float*)d_in[8];
    const float* opp_W1 = (const float*)d_in[9];
    const float* opp_b1 = (const float*)d_in[10];
    const float* opp_W2 = (const float*)d_in[11];
    const float* opp_b2 = (const float*)d_in[12];
    const float* pi_W1 = (const float*)d_in[13];
    const float* pi_b1 = (const float*)d_in[14];
    const float* pi_W2 = (const float*)d_in[15];
    const float* pi_b2 = (const float*)d_in[16];
    const float* pi_W3 = (const float*)d_in[17];
    const float* pi_b3 = (const float*)d_in[18];
    float* out = (float*)d_out;

    size_t smem = (size_t)(TM * OBS_LD + TM * ENC_LD + TM * H_LD) * sizeof(float);
    cudaFuncSetAttribute(mlpac_kernel, cudaFuncAttributeMaxDynamicSharedMemorySize,
                         (int)smem);
    dim3 grid(65536 / TM, 3, 1);
    mlpac_kernel<<<grid, NT, smem>>>(
        obs, prop_W1, prop_b1, prop_W2, prop_b2, ext_W1, ext_b1, ext_W2, ext_b2,
        opp_W1, opp_b1, opp_W2, opp_b2, pi_W1, pi_b1, pi_W2, pi_b2, pi_W3, pi_b3,
        out);
}

// round 4
// speedup vs baseline: 1.7103x; 1.0008x over previous
#include <cuda_runtime.h>
#include <math.h>

#define TM 64
#define NT 512
#define OBS_LD 52
#define ENC_LD 580
#define H_LD 260
#define T_LD 65

typedef unsigned long long u64;

__device__ __forceinline__ float lrelu(float x) { return fmaxf(x, 0.01f * x); }

__device__ __forceinline__ u64 pack2(float x) {
    u64 r;
    unsigned int b = __float_as_uint(x);
    asm("mov.b64 %0, {%1, %1};" : "=l"(r) : "r"(b));
    return r;
}
__device__ __forceinline__ void ffma2(u64& d, u64 a, u64 b) {
    asm("fma.rn.f32x2 %0, %1, %2, %3;" : "=l"(d) : "l"(a), "l"(b), "l"(d));
}
__device__ __forceinline__ float2 unpack2(u64 v) {
    unsigned int lo, hi;
    asm("mov.b64 {%0, %1}, %2;" : "=r"(lo), "=r"(hi) : "l"(v));
    return make_float2(__uint_as_float(lo), __uint_as_float(hi));
}

// ---------------------------------------------------------------------------
// layer1: [64 rows] x [K -> 32] + bias, lrelu. Output transposed s_t[toff+o][row].
// 512 thr: row = tid&63, 8 groups x 4 outputs (uniform W reads per group).
// ---------------------------------------------------------------------------
template <int K>
__device__ __forceinline__ void layer1(const float* __restrict__ s_obs, int in_off,
                                       const float* __restrict__ W1,
                                       const float* __restrict__ b1,
                                       float* __restrict__ s_t, int toff, int tid) {
    const int row = tid & 63;
    const int o0 = (tid >> 6) * 4;
    const float* x = s_obs + row * OBS_LD + in_off;
    float4 b = __ldg((const float4*)(b1 + o0));
    float acc[4] = {b.x, b.y, b.z, b.w};
#pragma unroll
    for (int k = 0; k < K; ++k) {
        float xv = x[k];
        float4 w = __ldg((const float4*)(W1 + k * 32 + o0));
        acc[0] = fmaf(xv, w.x, acc[0]);
        acc[1] = fmaf(xv, w.y, acc[1]);
        acc[2] = fmaf(xv, w.z, acc[2]);
        acc[3] = fmaf(xv, w.w, acc[3]);
    }
#pragma unroll
    for (int j = 0; j < 4; ++j)
        s_t[(toff + o0 + j) * T_LD + row] = lrelu(acc[j]);
}

// ---------------------------------------------------------------------------
// layer2: [64 rows] x [32 -> NV virtual cols] + bias, lrelu, store/add to enc.
// Virtual cols concatenate subnets of width SW (t rows: subnet s at s*32).
// 512 thr: 32 groups x 16 cols per sweep; thread rows {ra, +16, +32, +48}.
// f32x2 math; W reads uniform within each 16-thread group.
// ---------------------------------------------------------------------------
__device__ void layer2(const float* __restrict__ s_t,
                       const float* __restrict__ W2, const float* __restrict__ b2,
                       int SW, int NV, float* __restrict__ s_enc, int encbase,
                       bool add, int tid) {
    const int ra = tid & 15;
    const int g = tid >> 4;
    for (int c0 = g * 16; c0 < NV; c0 += 512) {
        const int s = c0 / SW;
        const int lc0 = c0 - s * SW;
        const float* W = W2 + s * 32 * SW + lc0;
        const float* tt = s_t + s * 32 * T_LD;

        u64 acc[4][8];
        {
            const float* bb = b2 + c0;
#pragma unroll
            for (int j = 0; j < 8; ++j) {
                u64 bp = ((const u64*)bb)[j];
#pragma unroll
                for (int m = 0; m < 4; ++m) acc[m][j] = bp;
            }
        }
#pragma unroll 2
        for (int k = 0; k < 32; ++k) {
            const float* wr = W + k * SW;
            ulonglong2 wa = __ldg((const ulonglong2*)(wr));
            ulonglong2 wb = __ldg((const ulonglong2*)(wr + 4));
            ulonglong2 wc = __ldg((const ulonglong2*)(wr + 8));
            ulonglong2 wd = __ldg((const ulonglong2*)(wr + 12));
            u64 w[8] = {wa.x, wa.y, wb.x, wb.y, wc.x, wc.y, wd.x, wd.y};
#pragma unroll
            for (int m = 0; m < 4; ++m) {
                u64 tp = pack2(tt[k * T_LD + ra + m * 16]);
#pragma unroll
                for (int j = 0; j < 8; ++j) ffma2(acc[m][j], tp, w[j]);
            }
        }
#pragma unroll
        for (int m = 0; m < 4; ++m) {
            float* e = s_enc + (ra + m * 16) * ENC_LD + encbase + c0;
            float v[16];
#pragma unroll
            for (int j = 0; j < 8; ++j) {
                float2 f = unpack2(acc[m][j]);
                v[2 * j] = lrelu(f.x);
                v[2 * j + 1] = lrelu(f.y);
            }
#pragma unroll
            for (int q = 0; q < 4; ++q) {
                float4 nv = make_float4(v[4 * q], v[4 * q + 1], v[4 * q + 2], v[4 * q + 3]);
                if (add) {
                    float4 old = *((float4*)(e + 4 * q));
                    nv.x += old.x; nv.y += old.y; nv.z += old.z; nv.w += old.w;
                }
                *((float4*)(e + 4 * q)) = nv;
            }
        }
    }
}

// ---------------------------------------------------------------------------
// gemm64x256: sOut[64][256] = lrelu(sA[64][K] * Wg[K][256] + bg).
// 16 warps, thread tile 4 rows x 8 cols (cols lane*4..+3 and 128+lane*4..+3).
// Chunk = 16 k-rows; each warp stages one row (lane covers 8 floats).
// Double-buffered with ONE __syncthreads per chunk. f32x2 accumulation.
// sOut may alias sBuf (written only after the loop's final barrier).
// ---------------------------------------------------------------------------
__device__ void gemm64x256(const float* __restrict__ sA, int lda, int K,
                           const float* __restrict__ Wg, const float* __restrict__ bg,
                           float* __restrict__ sBuf, float* __restrict__ sOut, int ldo,
                           int tid) {
    const int warp = tid >> 5;
    const int lane = tid & 31;
    const int r0 = warp * 4;
    const int cA = lane * 4;
    const int cB = 128 + lane * 4;
    const int sof = warp * 256 + lane * 8;

    u64 acc[4][4];
#pragma unroll
    for (int i = 0; i < 4; ++i)
#pragma unroll
        for (int j = 0; j < 4; ++j) acc[i][j] = 0ULL;

    const int NC = K >> 4;

    float4 p0 = __ldg((const float4*)(Wg + sof));
    float4 p1 = __ldg((const float4*)(Wg + sof + 4));
    *((float4*)(sBuf + sof)) = p0;
    *((float4*)(sBuf + sof + 4)) = p1;
    __syncthreads();

    for (int kc = 0; kc < NC; ++kc) {
        if (kc + 1 < NC) {
            const float* src = Wg + (kc + 1) * 4096 + sof;
            p0 = __ldg((const float4*)src);
            p1 = __ldg((const float4*)(src + 4));
        }
        const float* bufc = sBuf + (kc & 1) * 4096;
#pragma unroll
        for (int h = 0; h < 2; ++h) {
            float a[4][8];
#pragma unroll
            for (int i = 0; i < 4; ++i) {
                const float* ar = sA + (r0 + i) * lda + kc * 16 + h * 8;
                float4 x = *((const float4*)ar);
                float4 y = *((const float4*)(ar + 4));
                a[i][0] = x.x; a[i][1] = x.y; a[i][2] = x.z; a[i][3] = x.w;
                a[i][4] = y.x; a[i][5] = y.y; a[i][6] = y.z; a[i][7] = y.w;
            }
#pragma unroll
            for (int kk = 0; kk < 8; ++kk) {
                const float* wr = bufc + (h * 8 + kk) * 256;
                ulonglong2 w01 = *((const ulonglong2*)(wr + cA));
                ulonglong2 w23 = *((const ulonglong2*)(wr + cB));
#pragma unroll
                for (int i = 0; i < 4; ++i) {
                    u64 ap = pack2(a[i][kk]);
                    ffma2(acc[i][0], ap, w01.x);
                    ffma2(acc[i][1], ap, w01.y);
                    ffma2(acc[i][2], ap, w23.x);
                    ffma2(acc[i][3], ap, w23.y);
                }
            }
        }
        if (kc + 1 < NC) {
            float* dst = sBuf + ((kc + 1) & 1) * 4096 + sof;
            *((float4*)dst) = p0;
            *((float4*)(dst + 4)) = p1;
        }
        __syncthreads();
    }

    float4 bA = __ldg((const float4*)(bg + cA));
    float4 bB = __ldg((const float4*)(bg + cB));
#pragma unroll
    for (int i = 0; i < 4; ++i) {
        float2 f0 = unpack2(acc[i][0]);
        float2 f1 = unpack2(acc[i][1]);
        float2 f2 = unpack2(acc[i][2]);
        float2 f3 = unpack2(acc[i][3]);
        float4 oA = make_float4(lrelu(f0.x + bA.x), lrelu(f0.y + bA.y),
                                lrelu(f1.x + bA.z), lrelu(f1.y + bA.w));
        float4 oB = make_float4(lrelu(f2.x + bB.x), lrelu(f2.y + bB.y),
                                lrelu(f3.x + bB.z), lrelu(f3.y + bB.w));
        *((float4*)(sOut + (r0 + i) * ldo + cA)) = oA;
        *((float4*)(sOut + (r0 + i) * ldo + cB)) = oB;
    }
}

// ---------------------------------------------------------------------------
// Fused kernel: one CTA = 64 batch rows of one player, full network in SMEM.
// ---------------------------------------------------------------------------
__global__ void __launch_bounds__(NT, 1)
mlpac_kernel(const float* __restrict__ obs,
             const float* __restrict__ prop_W1, const float* __restrict__ prop_b1,
             const float* __restrict__ prop_W2, const float* __restrict__ prop_b2,
             const float* __restrict__ ext_W1, const float* __restrict__ ext_b1,
             const float* __restrict__ ext_W2, const float* __restrict__ ext_b2,
             const float* __restrict__ opp_W1, const float* __restrict__ opp_b1,
             const float* __restrict__ opp_W2, const float* __restrict__ opp_b2,
             const float* __restrict__ pi_W1, const float* __restrict__ pi_b1,
             const float* __restrict__ pi_W2, const float* __restrict__ pi_b2,
             const float* __restrict__ pi_W3, const float* __restrict__ pi_b3,
             float* __restrict__ out) {
    extern __shared__ float sm[];
    float* s_obs = sm;                       // 64*52  = 3328
    float* s_enc = sm + TM * OBS_LD;         // 64*580 = 37120
    float* s_h1 = s_enc + TM * ENC_LD;       // 64*260 = 16640
    float* s_t = s_h1;                       // encoder scratch alias (<=16640)

    const int tid = threadIdx.x;
    const int p = blockIdx.y;
    const int row0 = blockIdx.x * TM;

    // Load obs tile [64][48]
    for (int idx = tid; idx < TM * 12; idx += NT) {
        int r = idx / 12, c = (idx % 12) * 4;
        const float* src = obs + ((long)(row0 + r) * 3 + p) * 48 + c;
        *((float4*)(s_obs + r * OBS_LD + c)) = __ldg((const float4*)src);
    }
    __syncthreads();

    // ---- prop encoder: 9 subnets [2->32->64]; 8 at once, then 1
    {
        const float* W1 = prop_W1 + p * 9 * 64;
        const float* B1 = prop_b1 + p * 9 * 32;
        const float* W2 = prop_W2 + p * 9 * 2048;
        const float* B2 = prop_b2 + p * 576;
#pragma unroll
        for (int n = 0; n < 8; ++n)
            layer1<2>(s_obs, 2 * n, W1 + n * 64, B1 + n * 32, s_t, n * 32, tid);
        __syncthreads();
        layer2(s_t, W2, B2, 64, 512, s_enc, 0, false, tid);
        __syncthreads();
        layer1<2>(s_obs, 16, W1 + 8 * 64, B1 + 8 * 32, s_t, 0, tid);
        __syncthreads();
        layer2(s_t, W2 + 8 * 2048, B2 + 512, 64, 64, s_enc, 512, false, tid);
        __syncthreads();
    }
    // ---- ext encoder: 2 subnets [6->32->288] as one pair
    {
        const float* W1 = ext_W1 + p * 2 * 192;
        const float* B1 = ext_b1 + p * 64;
        const float* W2 = ext_W2 + p * 2 * 9216;
        const float* B2 = ext_b2 + p * 576;
        layer1<6>(s_obs, 18, W1, B1, s_t, 0, tid);
        layer1<6>(s_obs, 24, W1 + 192, B1 + 32, s_t, 32, tid);
        __syncthreads();
        layer2(s_t, W2, B2, 288, 576, s_enc, 0, true, tid);
        __syncthreads();
    }
    // ---- opp encoder: [18->32->576]
    layer1<18>(s_obs, 30, opp_W1 + p * 576, opp_b1 + p * 32, s_t, 0, tid);
    __syncthreads();
    layer2(s_t, opp_W2 + p * 32 * 576, opp_b2 + p * 576, 576, 576, s_enc, 0, true, tid);
    __syncthreads();

    // ---- pi1: enc[64][576] x W1[576][256] -> h1 (buf aliases s_h1)
    gemm64x256(s_enc, ENC_LD, 576, pi_W1 + p * 576 * 256, pi_b1 + p * 256,
               s_h1, s_h1, H_LD, tid);
    __syncthreads();
    // ---- pi2: h1 x W2[256][256] -> h2 in s_enc[0..], buf at s_enc+20480
    gemm64x256(s_h1, H_LD, 256, pi_W2 + p * 256 * 256, pi_b2 + p * 256,
               s_enc + 20480, s_enc, H_LD, tid);

    // ---- stage W3/b3 into s_obs (dead), then pi3 + tanh
    for (int i = tid; i < 768; i += NT) s_obs[i] = __ldg(pi_W3 + p * 768 + i);
    if (tid < 3) s_obs[768 + tid] = __ldg(pi_b3 + p * 3 + tid);
    __syncthreads();

    if (tid < 192) {
        int row = tid / 3, o = tid - row * 3;
        const float* h2 = s_enc + row * H_LD;
        float acc = s_obs[768 + o];
#pragma unroll 8
        for (int k = 0; k < 256; ++k)
            acc = fmaf(h2[k], s_obs[k * 3 + o], acc);
        out[((long)(row0 + row) * 3 + p) * 3 + o] = tanhf(acc);
    }
}

extern "C" void kernel_launch(void* const* d_in, const int* in_sizes, int n_in,
                              void* d_out, int out_size) {
    const float* obs = (const float*)d_in[0];
    const float* prop_W1 = (const float*)d_in[1];
    const float* prop_b1 = (const float*)d_in[2];
    const float* prop_W2 = (const float*)d_in[3];
    const float* prop_b2 = (const float*)d_in[4];
    const float* ext_W1 = (const float*)d_in[5];
    const float* ext_b1 = (const float*)d_in[6];
    const float* ext_W2 = (const float*)d_in[7];
    const float* ext_b2 = (const float*)d_in[8];
    const float* opp_W1 = (const float*)d_in[9];
    const float* opp_b1 = (const float*)d_in[10];
    const float* opp_W2 = (const float*)d_in[11];
    const float* opp_b2 = (const float*)d_in[12];
    const float* pi_W1 = (const float*)d_in[13];
    const float* pi_b1 = (const float*)d_in[14];
    const float* pi_W2 = (const float*)d_in[15];
    const float* pi_b2 = (const float*)d_in[16];
    const float* pi_W3 = (const float*)d_in[17];
    const float* pi_b3 = (const float*)d_in[18];
    float* out = (float*)d_out;

    size_t smem = (size_t)(TM * OBS_LD + TM * ENC_LD + TM * H_LD) * sizeof(float);
    cudaFuncSetAttribute(mlpac_kernel, cudaFuncAttributeMaxDynamicSharedMemorySize,
                         (int)smem);
    dim3 grid(65536 / TM, 3, 1);
    mlpac_kernel<<<grid, NT, smem>>>(
        obs, prop_W1, prop_b1, prop_W2, prop_b2, ext_W1, ext_b1, ext_W2, ext_b2,
        opp_W1, opp_b1, opp_W2, opp_b2, pi_W1, pi_b1, pi_W2, pi_b2, pi_W3, pi_b3,
        out);
}

// round 6
// speedup vs baseline: 2.3056x; 1.3481x over previous
#include <cuda_runtime.h>
#include <cuda_bf16.h>
#include <math.h>
#include <stdint.h>

#define TM 64
#define NT 512
#define OBS_LD 52
#define ENC_LD 580
#define H_LD 260
#define T_LD 65

// byte offsets in dynamic smem
#define A_HI_B 148480
#define A_LO_B 152576
#define B_HI_B 156672
#define B_LO_B 173056
#define OBS_B  215040
#define SMEM_B 228352

typedef unsigned long long u64;
typedef unsigned int u32;

__device__ __align__(16) __nv_bfloat16 g_B1h[3][256][576];
__device__ __align__(16) __nv_bfloat16 g_B1l[3][256][576];
__device__ __align__(16) __nv_bfloat16 g_B2h[3][256][256];
__device__ __align__(16) __nv_bfloat16 g_B2l[3][256][256];

__device__ __forceinline__ float lrelu(float x) { return fmaxf(x, 0.01f * x); }

__device__ __forceinline__ u64 pack2(float x) {
    u64 r; u32 b = __float_as_uint(x);
    asm("mov.b64 %0, {%1, %1};" : "=l"(r) : "r"(b));
    return r;
}
__device__ __forceinline__ void ffma2(u64& d, u64 a, u64 b) {
    asm("fma.rn.f32x2 %0, %1, %2, %3;" : "=l"(d) : "l"(a), "l"(b), "l"(d));
}
__device__ __forceinline__ float2 unpack2(u64 v) {
    u32 lo, hi;
    asm("mov.b64 {%0, %1}, %2;" : "=r"(lo), "=r"(hi) : "l"(v));
    return make_float2(__uint_as_float(lo), __uint_as_float(hi));
}
__device__ __forceinline__ u32 smem_u32(const void* p) {
    u32 a;
    asm("{ .reg .u64 t; cvta.to.shared.u64 t, %1; cvt.u32.u64 %0, t; }" : "=r"(a) : "l"(p));
    return a;
}
__device__ __forceinline__ u32 pkbf(__nv_bfloat16 a, __nv_bfloat16 b) {
    __nv_bfloat162 t(a, b);
    return *(u32*)&t;
}
// swizzled byte offset for 16B unit (row of 64B, unit u in 0..3)
__device__ __forceinline__ u32 swa(u32 base, int row, int u) {
    return base + row * 64 + ((u ^ ((row >> 1) & 3)) << 4);
}
__device__ __forceinline__ void ldm_x4(u32* r, u32 addr) {
    asm volatile("ldmatrix.sync.aligned.m8n8.x4.shared.b16 {%0,%1,%2,%3}, [%4];"
                 : "=r"(r[0]), "=r"(r[1]), "=r"(r[2]), "=r"(r[3]) : "r"(addr));
}
__device__ __forceinline__ void mma16816(float* d, const u32* a, u32 b0, u32 b1) {
    asm volatile(
        "mma.sync.aligned.m16n8k16.row.col.f32.bf16.bf16.f32 "
        "{%0,%1,%2,%3}, {%4,%5,%6,%7}, {%8,%9}, {%0,%1,%2,%3};"
        : "+f"(d[0]), "+f"(d[1]), "+f"(d[2]), "+f"(d[3])
        : "r"(a[0]), "r"(a[1]), "r"(a[2]), "r"(a[3]), "r"(b0), "r"(b1));
}

// ======================= encoder helpers (unchanged from R3) ================
template <int K>
__device__ __forceinline__ void layer1(const float* __restrict__ s_obs, int in_off,
                                       const float* __restrict__ W1,
                                       const float* __restrict__ b1,
                                       float* __restrict__ s_t, int toff, int tid) {
    const int row = tid & 63;
    const int o0 = (tid >> 6) * 4;
    const float* x = s_obs + row * OBS_LD + in_off;
    float4 b = __ldg((const float4*)(b1 + o0));
    float acc[4] = {b.x, b.y, b.z, b.w};
#pragma unroll
    for (int k = 0; k < K; ++k) {
        float xv = x[k];
        float4 w = __ldg((const float4*)(W1 + k * 32 + o0));
        acc[0] = fmaf(xv, w.x, acc[0]);
        acc[1] = fmaf(xv, w.y, acc[1]);
        acc[2] = fmaf(xv, w.z, acc[2]);
        acc[3] = fmaf(xv, w.w, acc[3]);
    }
#pragma unroll
    for (int j = 0; j < 4; ++j)
        s_t[(toff + o0 + j) * T_LD + row] = lrelu(acc[j]);
}

__device__ void layer2(const float* __restrict__ s_t,
                       const float* __restrict__ W2, const float* __restrict__ b2,
                       int SW, int NV, float* __restrict__ s_enc, int encbase,
                       bool add, int tid) {
    const int ra = tid & 15;
    const int g = tid >> 4;
    for (int c0 = g * 16; c0 < NV; c0 += 512) {
        const int s = c0 / SW;
        const int lc0 = c0 - s * SW;
        const float* W = W2 + s * 32 * SW + lc0;
        const float* tt = s_t + s * 32 * T_LD;

        u64 acc[4][8];
        {
            const float* bb = b2 + c0;
#pragma unroll
            for (int j = 0; j < 8; ++j) {
                u64 bp = ((const u64*)bb)[j];
#pragma unroll
                for (int m = 0; m < 4; ++m) acc[m][j] = bp;
            }
        }
#pragma unroll 2
        for (int k = 0; k < 32; ++k) {
            const float* wr = W + k * SW;
            ulonglong2 wa = __ldg((const ulonglong2*)(wr));
            ulonglong2 wb = __ldg((const ulonglong2*)(wr + 4));
            ulonglong2 wc = __ldg((const ulonglong2*)(wr + 8));
            ulonglong2 wd = __ldg((const ulonglong2*)(wr + 12));
            u64 w[8] = {wa.x, wa.y, wb.x, wb.y, wc.x, wc.y, wd.x, wd.y};
#pragma unroll
            for (int m = 0; m < 4; ++m) {
                u64 tp = pack2(tt[k * T_LD + ra + m * 16]);
#pragma unroll
                for (int j = 0; j < 8; ++j) ffma2(acc[m][j], tp, w[j]);
            }
        }
#pragma unroll
        for (int m = 0; m < 4; ++m) {
            float* e = s_enc + (ra + m * 16) * ENC_LD + encbase + c0;
            float v[16];
#pragma unroll
            for (int j = 0; j < 8; ++j) {
                float2 f = unpack2(acc[m][j]);
                v[2 * j] = lrelu(f.x);
                v[2 * j + 1] = lrelu(f.y);
            }
#pragma unroll
            for (int q = 0; q < 4; ++q) {
                float4 nv = make_float4(v[4 * q], v[4 * q + 1], v[4 * q + 2], v[4 * q + 3]);
                if (add) {
                    float4 old = *((float4*)(e + 4 * q));
                    nv.x += old.x; nv.y += old.y; nv.z += old.z; nv.w += old.w;
                }
                *((float4*)(e + 4 * q)) = nv;
            }
        }
    }
}

// ======================= HMMA pi GEMM =======================================
// sOut[64][ldo] = lrelu(sA[64][Kt] * Bt^T + bias). Bt hi/lo bf16 [256][Kt].
// Per K=32 chunk: stage B hi/lo to smem (swizzled), convert A fp32 -> hi/lo
// bf16 tiles; 16 warps each compute m32 x n32 with mma.m16n8k16 (3-product
// hi/lo split). Accumulators in registers; readout applies bias + lrelu.
// sOut may alias sA (written only after the final barrier).
__device__ void pi_gemm(const float* __restrict__ sA, int lda, int Kt,
                        const __nv_bfloat16* __restrict__ Bh,
                        const __nv_bfloat16* __restrict__ Bl,
                        const float* __restrict__ sBias,
                        float* __restrict__ sOut, int ldo,
                        char* smc, u32 sbase, int tid) {
    const int w = tid >> 5, lane = tid & 31;
    const int m0w = (w & 1) * 32;
    const int n0w = (w >> 1) * 32;
    const int fr = ((lane >> 3) & 1) * 8 + (lane & 7);  // ldmatrix row-in-tile
    const int fu = lane >> 4;                            // ldmatrix k-half

    float d[2][4][4];
#pragma unroll
    for (int i = 0; i < 2; ++i)
#pragma unroll
        for (int j = 0; j < 4; ++j)
#pragma unroll
            for (int q = 0; q < 4; ++q) d[i][j][q] = 0.f;

    const int NCh = Kt >> 5;
    for (int kc = 0; kc < NCh; ++kc) {
        __syncthreads();
        // ---- convert A chunk [64][32] fp32 -> hi/lo bf16 (threads 0-255)
        if (tid < 256) {
            int row = tid >> 2, u = tid & 3;
            const float* src = sA + row * lda + kc * 32 + u * 8;
            float4 X = *(const float4*)src;
            float4 Y = *(const float4*)(src + 4);
            float x[8] = {X.x, X.y, X.z, X.w, Y.x, Y.y, Y.z, Y.w};
            u32 hw[4], lw[4];
#pragma unroll
            for (int j = 0; j < 4; ++j) {
                __nv_bfloat16 h0 = __float2bfloat16(x[2 * j]);
                __nv_bfloat16 h1 = __float2bfloat16(x[2 * j + 1]);
                __nv_bfloat16 l0 = __float2bfloat16(x[2 * j] - __bfloat162float(h0));
                __nv_bfloat16 l1 = __float2bfloat16(x[2 * j + 1] - __bfloat162float(h1));
                hw[j] = pkbf(h0, h1);
                lw[j] = pkbf(l0, l1);
            }
            *(uint4*)(smc + swa(A_HI_B, row, u)) = make_uint4(hw[0], hw[1], hw[2], hw[3]);
            *(uint4*)(smc + swa(A_LO_B, row, u)) = make_uint4(lw[0], lw[1], lw[2], lw[3]);
        }
        // ---- stage B chunk [256][32] hi/lo from global
#pragma unroll
        for (int m = 0; m < 2; ++m) {
            int idx = tid + m * 512;
            int row = idx >> 2, u = idx & 3;
            long go = (long)row * Kt + kc * 32 + u * 8;
            uint4 hv = *(const uint4*)(Bh + go);
            uint4 lv = *(const uint4*)(Bl + go);
            *(uint4*)(smc + swa(B_HI_B, row, u)) = hv;
            *(uint4*)(smc + swa(B_LO_B, row, u)) = lv;
        }
        __syncthreads();
        // ---- two k16 steps
#pragma unroll
        for (int ks = 0; ks < 2; ++ks) {
            const int ua = ks * 2 + fu;
            u32 ah[2][4], al[2][4], bh[2][4], bl[2][4];
#pragma unroll
            for (int mt = 0; mt < 2; ++mt) {
                int r = m0w + mt * 16 + fr;
                ldm_x4(ah[mt], sbase + swa(A_HI_B, r, ua));
                ldm_x4(al[mt], sbase + swa(A_LO_B, r, ua));
            }
#pragma unroll
            for (int nh = 0; nh < 2; ++nh) {
                int r = n0w + nh * 16 + fr;
                ldm_x4(bh[nh], sbase + swa(B_HI_B, r, ua));
                ldm_x4(bl[nh], sbase + swa(B_LO_B, r, ua));
            }
#pragma unroll
            for (int mt = 0; mt < 2; ++mt)
#pragma unroll
                for (int nt = 0; nt < 4; ++nt) {
                    int nh = nt >> 1, hf = nt & 1;
                    mma16816(d[mt][nt], ah[mt], bh[nh][hf], bh[nh][2 + hf]);
                    mma16816(d[mt][nt], ah[mt], bl[nh][hf], bl[nh][2 + hf]);
                    mma16816(d[mt][nt], al[mt], bh[nh][hf], bh[nh][2 + hf]);
                }
        }
    }
    __syncthreads();
    // ---- readout: bias + lrelu -> sOut
#pragma unroll
    for (int mt = 0; mt < 2; ++mt)
#pragma unroll
        for (int nt = 0; nt < 4; ++nt) {
            int col = n0w + nt * 8 + (lane & 3) * 2;
            int row = m0w + mt * 16 + (lane >> 2);
            float2 b = *(const float2*)(sBias + col);
            *(float2*)(sOut + row * ldo + col) =
                make_float2(lrelu(d[mt][nt][0] + b.x), lrelu(d[mt][nt][1] + b.y));
            *(float2*)(sOut + (row + 8) * ldo + col) =
                make_float2(lrelu(d[mt][nt][2] + b.x), lrelu(d[mt][nt][3] + b.y));
        }
    __syncthreads();
}

// ======================= prep: transpose + hi/lo split pi weights ===========
__global__ void prep_kernel(const float* __restrict__ W1, const float* __restrict__ W2) {
    int i = blockIdx.x * 256 + threadIdx.x;
    if (i < 3 * 576 * 256) {
        int p = i / (576 * 256), rem = i % (576 * 256);
        int k = rem / 256, n = rem % 256;
        float w = __ldg(W1 + i);
        __nv_bfloat16 h = __float2bfloat16(w);
        g_B1h[p][n][k] = h;
        g_B1l[p][n][k] = __float2bfloat16(w - __bfloat162float(h));
    }
    if (i < 3 * 256 * 256) {
        int p = i / (256 * 256), rem = i % (256 * 256);
        int k = rem / 256, n = rem % 256;
        float w = __ldg(W2 + i);
        __nv_bfloat16 h = __float2bfloat16(w);
        g_B2h[p][n][k] = h;
        g_B2l[p][n][k] = __float2bfloat16(w - __bfloat162float(h));
    }
}

// ======================= fused kernel =======================================
__global__ void __launch_bounds__(NT, 1)
mlpac_kernel(const float* __restrict__ obs,
             const float* __restrict__ prop_W1, const float* __restrict__ prop_b1,
             const float* __restrict__ prop_W2, const float* __restrict__ prop_b2,
             const float* __restrict__ ext_W1, const float* __restrict__ ext_b1,
             const float* __restrict__ ext_W2, const float* __restrict__ ext_b2,
             const float* __restrict__ opp_W1, const float* __restrict__ opp_b1,
             const float* __restrict__ opp_W2, const float* __restrict__ opp_b2,
             const float* __restrict__ pi_W1, const float* __restrict__ pi_b1,
             const float* __restrict__ pi_W2, const float* __restrict__ pi_b2,
             const float* __restrict__ pi_W3, const float* __restrict__ pi_b3,
             float* __restrict__ out) {
    extern __shared__ float sm[];
    char* smc = (char*)sm;
    float* s_enc = sm;                   // [64][580] fp32, bytes [0, 148480)
    float* s_t = sm + 37120;             // encoder scratch [256][65]; aliases mma stage
    float* s_obs = sm + 53760;           // [64][52] fp32; later pi consts
    u32 sbase = smem_u32(sm);

    const int tid = threadIdx.x;
    const int p = blockIdx.y;
    const int row0 = blockIdx.x * TM;

    for (int idx = tid; idx < TM * 12; idx += NT) {
        int r = idx / 12, c = (idx % 12) * 4;
        const float* src = obs + ((long)(row0 + r) * 3 + p) * 48 + c;
        *((float4*)(s_obs + r * OBS_LD + c)) = __ldg((const float4*)src);
    }
    __syncthreads();

    // ---- prop encoder: 9 subnets [2->32->64]; 8 at once, then 1
    {
        const float* W1 = prop_W1 + p * 9 * 64;
        const float* B1 = prop_b1 + p * 9 * 32;
        const float* W2 = prop_W2 + p * 9 * 2048;
        const float* B2 = prop_b2 + p * 576;
#pragma unroll
        for (int n = 0; n < 8; ++n)
            layer1<2>(s_obs, 2 * n, W1 + n * 64, B1 + n * 32, s_t, n * 32, tid);
        __syncthreads();
        layer2(s_t, W2, B2, 64, 512, s_enc, 0, false, tid);
        __syncthreads();
        layer1<2>(s_obs, 16, W1 + 8 * 64, B1 + 8 * 32, s_t, 0, tid);
        __syncthreads();
        layer2(s_t, W2 + 8 * 2048, B2 + 512, 64, 64, s_enc, 512, false, tid);
        __syncthreads();
    }
    // ---- ext encoder: 2 subnets [6->32->288]
    {
        const float* W1 = ext_W1 + p * 2 * 192;
        const float* B1 = ext_b1 + p * 64;
        const float* W2 = ext_W2 + p * 2 * 9216;
        const float* B2 = ext_b2 + p * 576;
        layer1<6>(s_obs, 18, W1, B1, s_t, 0, tid);
        layer1<6>(s_obs, 24, W1 + 192, B1 + 32, s_t, 32, tid);
        __syncthreads();
        layer2(s_t, W2, B2, 288, 576, s_enc, 0, true, tid);
        __syncthreads();
    }
    // ---- opp encoder: [18->32->576]
    layer1<18>(s_obs, 30, opp_W1 + p * 576, opp_b1 + p * 32, s_t, 0, tid);
    __syncthreads();
    layer2(s_t, opp_W2 + p * 32 * 576, opp_b2 + p * 576, 576, 576, s_enc, 0, true, tid);
    // stage pi constants into s_obs (obs dead; layer2 does not touch s_obs)
    for (int i = tid; i < 256; i += NT) s_obs[i] = __ldg(pi_b1 + p * 256 + i);
    for (int i = tid; i < 256; i += NT) s_obs[256 + i] = __ldg(pi_b2 + p * 256 + i);
    for (int i = tid; i < 768; i += NT) s_obs[512 + i] = __ldg(pi_W3 + p * 768 + i);
    if (tid < 3) s_obs[1280 + tid] = __ldg(pi_b3 + p * 3 + tid);

    // ---- pi1: enc[64][576] @ W1 -> h1 at enc base (alias-safe)
    pi_gemm(s_enc, ENC_LD, 576, &g_B1h[p][0][0], &g_B1l[p][0][0],
            s_obs, s_enc, H_LD, smc, sbase, tid);
    // ---- pi2: h1[64][260] @ W2 -> h2 at enc+16640
    pi_gemm(s_enc, H_LD, 256, &g_B2h[p][0][0], &g_B2l[p][0][0],
            s_obs + 256, s_enc + 16640, H_LD, smc, sbase, tid);

    // ---- pi3 + tanh
    if (tid < 192) {
        int row = tid / 3, o = tid - row * 3;
        const float* h2 = s_enc + 16640 + row * H_LD;
        float acc = s_obs[1280 + o];
#pragma unroll 8
        for (int k = 0; k < 256; ++k)
            acc = fmaf(h2[k], s_obs[512 + k * 3 + o], acc);
        out[((long)(row0 + row) * 3 + p) * 3 + o] = tanhf(acc);
    }
}

extern "C" void kernel_launch(void* const* d_in, const int* in_sizes, int n_in,
                              void* d_out, int out_size) {
    const float* obs = (const float*)d_in[0];
    const float* prop_W1 = (const float*)d_in[1];
    const float* prop_b1 = (const float*)d_in[2];
    const float* prop_W2 = (const float*)d_in[3];
    const float* prop_b2 = (const float*)d_in[4];
    const float* ext_W1 = (const float*)d_in[5];
    const float* ext_b1 = (const float*)d_in[6];
    const float* ext_W2 = (const float*)d_in[7];
    const float* ext_b2 = (const float*)d_in[8];
    const float* opp_W1 = (const float*)d_in[9];
    const float* opp_b1 = (const float*)d_in[10];
    const float* opp_W2 = (const float*)d_in[11];
    const float* opp_b2 = (const float*)d_in[12];
    const float* pi_W1 = (const float*)d_in[13];
    const float* pi_b1 = (const float*)d_in[14];
    const float* pi_W2 = (const float*)d_in[15];
    const float* pi_b2 = (const float*)d_in[16];
    const float* pi_W3 = (const float*)d_in[17];
    const float* pi_b3 = (const float*)d_in[18];
    float* out = (float*)d_out;

    prep_kernel<<<1728, 256>>>(pi_W1, pi_W2);

    cudaFuncSetAttribute(mlpac_kernel, cudaFuncAttributeMaxDynamicSharedMemorySize, SMEM_B);
    dim3 grid(65536 / TM, 3, 1);
    mlpac_kernel<<<grid, NT, SMEM_B>>>(
        obs, prop_W1, prop_b1, prop_W2, prop_b2, ext_W1, ext_b1, ext_W2, ext_b2,
        opp_W1, opp_b1, opp_W2, opp_b2, pi_W1, pi_b1, pi_W2, pi_b2, pi_W3, pi_b3,
        out);
}

// round 7
// speedup vs baseline: 2.4779x; 1.0747x over previous
#include <cuda_runtime.h>
#include <cuda_bf16.h>
#include <math.h>
#include <stdint.h>

#define TM 64
#define NT 512
#define OBS_LD 52
#define ENC_LD 580
#define H_LD 260
#define T_LD 65

// byte offsets in dynamic smem
#define A_HI_B 148480
#define A_LO_B 152576
#define B_HI_B 156672
#define B_LO_B 173056
#define SMEM_B 228352

typedef unsigned long long u64;
typedef unsigned int u32;

__device__ __align__(16) __nv_bfloat16 g_B1h[3][256][576];
__device__ __align__(16) __nv_bfloat16 g_B1l[3][256][576];
__device__ __align__(16) __nv_bfloat16 g_B2h[3][256][256];
__device__ __align__(16) __nv_bfloat16 g_B2l[3][256][256];

__device__ __forceinline__ float lrelu(float x) { return fmaxf(x, 0.01f * x); }

__device__ __forceinline__ u64 pack2(float x) {
    u64 r; u32 b = __float_as_uint(x);
    asm("mov.b64 %0, {%1, %1};" : "=l"(r) : "r"(b));
    return r;
}
__device__ __forceinline__ void ffma2(u64& d, u64 a, u64 b) {
    asm("fma.rn.f32x2 %0, %1, %2, %3;" : "=l"(d) : "l"(a), "l"(b), "l"(d));
}
__device__ __forceinline__ float2 unpack2(u64 v) {
    u32 lo, hi;
    asm("mov.b64 {%0, %1}, %2;" : "=r"(lo), "=r"(hi) : "l"(v));
    return make_float2(__uint_as_float(lo), __uint_as_float(hi));
}
__device__ __forceinline__ u32 smem_u32(const void* p) {
    u32 a;
    asm("{ .reg .u64 t; cvta.to.shared.u64 t, %1; cvt.u32.u64 %0, t; }" : "=r"(a) : "l"(p));
    return a;
}
__device__ __forceinline__ u32 pkbf(__nv_bfloat16 a, __nv_bfloat16 b) {
    __nv_bfloat162 t(a, b);
    return *(u32*)&t;
}
// swizzled byte offset for 16B unit (row of 64B, unit u in 0..3)
__device__ __forceinline__ u32 swa(u32 base, int row, int u) {
    return base + row * 64 + ((u ^ ((row >> 1) & 3)) << 4);
}
__device__ __forceinline__ void ldm_x4(u32* r, u32 addr) {
    asm volatile("ldmatrix.sync.aligned.m8n8.x4.shared.b16 {%0,%1,%2,%3}, [%4];"
                 : "=r"(r[0]), "=r"(r[1]), "=r"(r[2]), "=r"(r[3]) : "r"(addr));
}
__device__ __forceinline__ void mma16816(float* d, const u32* a, u32 b0, u32 b1) {
    asm volatile(
        "mma.sync.aligned.m16n8k16.row.col.f32.bf16.bf16.f32 "
        "{%0,%1,%2,%3}, {%4,%5,%6,%7}, {%8,%9}, {%0,%1,%2,%3};"
        : "+f"(d[0]), "+f"(d[1]), "+f"(d[2]), "+f"(d[3])
        : "r"(a[0]), "r"(a[1]), "r"(a[2]), "r"(a[3]), "r"(b0), "r"(b1));
}
__device__ __forceinline__ void split8(const float* x, uint4& hi, uint4& lo) {
    u32 hw[4], lw[4];
#pragma unroll
    for (int j = 0; j < 4; ++j) {
        __nv_bfloat16 h0 = __float2bfloat16(x[2 * j]);
        __nv_bfloat16 h1 = __float2bfloat16(x[2 * j + 1]);
        __nv_bfloat16 l0 = __float2bfloat16(x[2 * j] - __bfloat162float(h0));
        __nv_bfloat16 l1 = __float2bfloat16(x[2 * j + 1] - __bfloat162float(h1));
        hw[j] = pkbf(h0, h1);
        lw[j] = pkbf(l0, l1);
    }
    hi = make_uint4(hw[0], hw[1], hw[2], hw[3]);
    lo = make_uint4(lw[0], lw[1], lw[2], lw[3]);
}

// ======================= encoder helpers (unchanged) ========================
template <int K>
__device__ __forceinline__ void layer1(const float* __restrict__ s_obs, int in_off,
                                       const float* __restrict__ W1,
                                       const float* __restrict__ b1,
                                       float* __restrict__ s_t, int toff, int tid) {
    const int row = tid & 63;
    const int o0 = (tid >> 6) * 4;
    const float* x = s_obs + row * OBS_LD + in_off;
    float4 b = __ldg((const float4*)(b1 + o0));
    float acc[4] = {b.x, b.y, b.z, b.w};
#pragma unroll
    for (int k = 0; k < K; ++k) {
        float xv = x[k];
        float4 w = __ldg((const float4*)(W1 + k * 32 + o0));
        acc[0] = fmaf(xv, w.x, acc[0]);
        acc[1] = fmaf(xv, w.y, acc[1]);
        acc[2] = fmaf(xv, w.z, acc[2]);
        acc[3] = fmaf(xv, w.w, acc[3]);
    }
#pragma unroll
    for (int j = 0; j < 4; ++j)
        s_t[(toff + o0 + j) * T_LD + row] = lrelu(acc[j]);
}

__device__ void layer2(const float* __restrict__ s_t,
                       const float* __restrict__ W2, const float* __restrict__ b2,
                       int SW, int NV, float* __restrict__ s_enc, int encbase,
                       bool add, int tid) {
    const int ra = tid & 15;
    const int g = tid >> 4;
    for (int c0 = g * 16; c0 < NV; c0 += 512) {
        const int s = c0 / SW;
        const int lc0 = c0 - s * SW;
        const float* W = W2 + s * 32 * SW + lc0;
        const float* tt = s_t + s * 32 * T_LD;

        u64 acc[4][8];
        {
            const float* bb = b2 + c0;
#pragma unroll
            for (int j = 0; j < 8; ++j) {
                u64 bp = ((const u64*)bb)[j];
#pragma unroll
                for (int m = 0; m < 4; ++m) acc[m][j] = bp;
            }
        }
#pragma unroll 2
        for (int k = 0; k < 32; ++k) {
            const float* wr = W + k * SW;
            ulonglong2 wa = __ldg((const ulonglong2*)(wr));
            ulonglong2 wb = __ldg((const ulonglong2*)(wr + 4));
            ulonglong2 wc = __ldg((const ulonglong2*)(wr + 8));
            ulonglong2 wd = __ldg((const ulonglong2*)(wr + 12));
            u64 w[8] = {wa.x, wa.y, wb.x, wb.y, wc.x, wc.y, wd.x, wd.y};
#pragma unroll
            for (int m = 0; m < 4; ++m) {
                u64 tp = pack2(tt[k * T_LD + ra + m * 16]);
#pragma unroll
                for (int j = 0; j < 8; ++j) ffma2(acc[m][j], tp, w[j]);
            }
        }
#pragma unroll
        for (int m = 0; m < 4; ++m) {
            float* e = s_enc + (ra + m * 16) * ENC_LD + encbase + c0;
            float v[16];
#pragma unroll
            for (int j = 0; j < 8; ++j) {
                float2 f = unpack2(acc[m][j]);
                v[2 * j] = lrelu(f.x);
                v[2 * j + 1] = lrelu(f.y);
            }
#pragma unroll
            for (int q = 0; q < 4; ++q) {
                float4 nv = make_float4(v[4 * q], v[4 * q + 1], v[4 * q + 2], v[4 * q + 3]);
                if (add) {
                    float4 old = *((float4*)(e + 4 * q));
                    nv.x += old.x; nv.y += old.y; nv.z += old.z; nv.w += old.w;
                }
                *((float4*)(e + 4 * q)) = nv;
            }
        }
    }
}

// ======================= HMMA pi GEMM (software-pipelined) ==================
// sOut[64][ldo] = lrelu(sA[64][Kt] * Bt^T + bias). Bt hi/lo bf16 [256][Kt].
// Register-prefetch of next chunk's B (LDG) and A (LDS fp32) overlaps the
// current chunk's ldmatrix+mma. All smem addresses are loop-invariant.
__device__ void pi_gemm(const float* __restrict__ sA, int lda, int Kt,
                        const __nv_bfloat16* __restrict__ Bh,
                        const __nv_bfloat16* __restrict__ Bl,
                        const float* __restrict__ sBias,
                        float* __restrict__ sOut, int ldo,
                        char* smc, u32 sbase, int tid) {
    const int w = tid >> 5, lane = tid & 31;
    const int m0w = (w & 1) * 32;
    const int n0w = (w >> 1) * 32;
    const int fr = ((lane >> 3) & 1) * 8 + (lane & 7);
    const int fu = lane >> 4;

    // ---- loop-invariant ldmatrix addresses [ks][tile]
    u32 adAh[2][2], adAl[2][2], adBh[2][2], adBl[2][2];
#pragma unroll
    for (int ks = 0; ks < 2; ++ks) {
        int ua = ks * 2 + fu;
#pragma unroll
        for (int t = 0; t < 2; ++t) {
            int rm = m0w + t * 16 + fr;
            int rn = n0w + t * 16 + fr;
            adAh[ks][t] = sbase + swa(A_HI_B, rm, ua);
            adAl[ks][t] = sbase + swa(A_LO_B, rm, ua);
            adBh[ks][t] = sbase + swa(B_HI_B, rn, ua);
            adBl[ks][t] = sbase + swa(B_LO_B, rn, ua);
        }
    }
    // ---- loop-invariant STS addresses + source pointers
    const int crow = tid >> 2, cu = tid & 3;          // A role (tid<256)
    const u32 stAh = sbase + swa(A_HI_B, crow & 63, cu);
    const u32 stAl = sbase + swa(A_LO_B, crow & 63, cu);
    const float* asrc = sA + (crow & 63) * lda + cu * 8;
    const int br0 = tid >> 2, bu0 = tid & 3;          // B role unit 0
    const int br1 = (tid + 512) >> 2, bu1 = tid & 3;  // B role unit 1
    const u32 stBh0 = sbase + swa(B_HI_B, br0, bu0);
    const u32 stBl0 = sbase + swa(B_LO_B, br0, bu0);
    const u32 stBh1 = sbase + swa(B_HI_B, br1, bu1);
    const u32 stBl1 = sbase + swa(B_LO_B, br1, bu1);
    const __nv_bfloat16* bsrcH0 = Bh + (long)br0 * Kt + bu0 * 8;
    const __nv_bfloat16* bsrcL0 = Bl + (long)br0 * Kt + bu0 * 8;
    const __nv_bfloat16* bsrcH1 = Bh + (long)br1 * Kt + bu1 * 8;
    const __nv_bfloat16* bsrcL1 = Bl + (long)br1 * Kt + bu1 * 8;

    float d[2][4][4];
#pragma unroll
    for (int i = 0; i < 2; ++i)
#pragma unroll
        for (int j = 0; j < 4; ++j)
#pragma unroll
            for (int q = 0; q < 4; ++q) d[i][j][q] = 0.f;

    const int NCh = Kt >> 5;

    __syncthreads();  // enc/h1 fully written before prefetch reads it

    // ---- prefetch chunk 0
    uint4 pBh0 = *(const uint4*)(bsrcH0);
    uint4 pBl0 = *(const uint4*)(bsrcL0);
    uint4 pBh1 = *(const uint4*)(bsrcH1);
    uint4 pBl1 = *(const uint4*)(bsrcL1);
    float4 pA0, pA1;
    if (tid < 256) { pA0 = *(const float4*)asrc; pA1 = *(const float4*)(asrc + 4); }

    for (int kc = 0; kc < NCh; ++kc) {
        __syncthreads();  // prior chunk's ldmatrix reads complete
        if (tid < 256) {
            float x[8] = {pA0.x, pA0.y, pA0.z, pA0.w, pA1.x, pA1.y, pA1.z, pA1.w};
            uint4 hi, lo;
            split8(x, hi, lo);
            *(uint4*)(smc + (stAh - sbase)) = hi;
            *(uint4*)(smc + (stAl - sbase)) = lo;
        }
        *(uint4*)(smc + (stBh0 - sbase)) = pBh0;
        *(uint4*)(smc + (stBl0 - sbase)) = pBl0;
        *(uint4*)(smc + (stBh1 - sbase)) = pBh1;
        *(uint4*)(smc + (stBl1 - sbase)) = pBl1;
        __syncthreads();  // tiles ready
        if (kc + 1 < NCh) {  // prefetch next chunk (latency hidden by mma below)
            int ko = (kc + 1) * 32;
            pBh0 = *(const uint4*)(bsrcH0 + ko);
            pBl0 = *(const uint4*)(bsrcL0 + ko);
            pBh1 = *(const uint4*)(bsrcH1 + ko);
            pBl1 = *(const uint4*)(bsrcL1 + ko);
            if (tid < 256) {
                pA0 = *(const float4*)(asrc + ko);
                pA1 = *(const float4*)(asrc + ko + 4);
            }
        }
#pragma unroll
        for (int ks = 0; ks < 2; ++ks) {
            u32 ah[2][4], al[2][4], bh[2][4], bl[2][4];
#pragma unroll
            for (int t = 0; t < 2; ++t) {
                ldm_x4(ah[t], adAh[ks][t]);
                ldm_x4(al[t], adAl[ks][t]);
                ldm_x4(bh[t], adBh[ks][t]);
                ldm_x4(bl[t], adBl[ks][t]);
            }
#pragma unroll
            for (int mt = 0; mt < 2; ++mt)
#pragma unroll
                for (int nt = 0; nt < 4; ++nt) {
                    int nh = nt >> 1, hf = nt & 1;
                    mma16816(d[mt][nt], ah[mt], bh[nh][hf], bh[nh][2 + hf]);
                    mma16816(d[mt][nt], ah[mt], bl[nh][hf], bl[nh][2 + hf]);
                    mma16816(d[mt][nt], al[mt], bh[nh][hf], bh[nh][2 + hf]);
                }
        }
    }
    __syncthreads();
    // ---- readout: bias + lrelu -> sOut
#pragma unroll
    for (int mt = 0; mt < 2; ++mt)
#pragma unroll
        for (int nt = 0; nt < 4; ++nt) {
            int col = n0w + nt * 8 + (lane & 3) * 2;
            int row = m0w + mt * 16 + (lane >> 2);
            float2 b = *(const float2*)(sBias + col);
            *(float2*)(sOut + row * ldo + col) =
                make_float2(lrelu(d[mt][nt][0] + b.x), lrelu(d[mt][nt][1] + b.y));
            *(float2*)(sOut + (row + 8) * ldo + col) =
                make_float2(lrelu(d[mt][nt][2] + b.x), lrelu(d[mt][nt][3] + b.y));
        }
    __syncthreads();
}

// ======================= prep: transpose + hi/lo split pi weights ===========
__global__ void prep_kernel(const float* __restrict__ W1, const float* __restrict__ W2) {
    int i = blockIdx.x * 256 + threadIdx.x;
    if (i < 3 * 576 * 256) {
        int p = i / (576 * 256), rem = i % (576 * 256);
        int k = rem / 256, n = rem % 256;
        float w = __ldg(W1 + i);
        __nv_bfloat16 h = __float2bfloat16(w);
        g_B1h[p][n][k] = h;
        g_B1l[p][n][k] = __float2bfloat16(w - __bfloat162float(h));
    }
    if (i < 3 * 256 * 256) {
        int p = i / (256 * 256), rem = i % (256 * 256);
        int k = rem / 256, n = rem % 256;
        float w = __ldg(W2 + i);
        __nv_bfloat16 h = __float2bfloat16(w);
        g_B2h[p][n][k] = h;
        g_B2l[p][n][k] = __float2bfloat16(w - __bfloat162float(h));
    }
}

// ======================= fused kernel =======================================
__global__ void __launch_bounds__(NT, 1)
mlpac_kernel(const float* __restrict__ obs,
             const float* __restrict__ prop_W1, const float* __restrict__ prop_b1,
             const float* __restrict__ prop_W2, const float* __restrict__ prop_b2,
             const float* __restrict__ ext_W1, const float* __restrict__ ext_b1,
             const float* __restrict__ ext_W2, const float* __restrict__ ext_b2,
             const float* __restrict__ opp_W1, const float* __restrict__ opp_b1,
             const float* __restrict__ opp_W2, const float* __restrict__ opp_b2,
             const float* __restrict__ pi_W1, const float* __restrict__ pi_b1,
             const float* __restrict__ pi_W2, const float* __restrict__ pi_b2,
             const float* __restrict__ pi_W3, const float* __restrict__ pi_b3,
             float* __restrict__ out) {
    extern __shared__ float sm[];
    char* smc = (char*)sm;
    float* s_enc = sm;                   // [64][580] fp32, bytes [0, 148480)
    float* s_t = sm + 37120;             // encoder scratch [256][65]; aliases mma stage
    float* s_obs = sm + 53760;           // [64][52] fp32; later pi consts
    u32 sbase = smem_u32(sm);

    const int tid = threadIdx.x;
    const int p = blockIdx.y;
    const int row0 = blockIdx.x * TM;

    for (int idx = tid; idx < TM * 12; idx += NT) {
        int r = idx / 12, c = (idx % 12) * 4;
        const float* src = obs + ((long)(row0 + r) * 3 + p) * 48 + c;
        *((float4*)(s_obs + r * OBS_LD + c)) = __ldg((const float4*)src);
    }
    __syncthreads();

    // ---- prop encoder: 9 subnets [2->32->64]; 8 at once, then 1
    {
        const float* W1 = prop_W1 + p * 9 * 64;
        const float* B1 = prop_b1 + p * 9 * 32;
        const float* W2 = prop_W2 + p * 9 * 2048;
        const float* B2 = prop_b2 + p * 576;
#pragma unroll
        for (int n = 0; n < 8; ++n)
            layer1<2>(s_obs, 2 * n, W1 + n * 64, B1 + n * 32, s_t, n * 32, tid);
        __syncthreads();
        layer2(s_t, W2, B2, 64, 512, s_enc, 0, false, tid);
        __syncthreads();
        layer1<2>(s_obs, 16, W1 + 8 * 64, B1 + 8 * 32, s_t, 0, tid);
        __syncthreads();
        layer2(s_t, W2 + 8 * 2048, B2 + 512, 64, 64, s_enc, 512, false, tid);
        __syncthreads();
    }
    // ---- ext encoder: 2 subnets [6->32->288]
    {
        const float* W1 = ext_W1 + p * 2 * 192;
        const float* B1 = ext_b1 + p * 64;
        const float* W2 = ext_W2 + p * 2 * 9216;
        const float* B2 = ext_b2 + p * 576;
        layer1<6>(s_obs, 18, W1, B1, s_t, 0, tid);
        layer1<6>(s_obs, 24, W1 + 192, B1 + 32, s_t, 32, tid);
        __syncthreads();
        layer2(s_t, W2, B2, 288, 576, s_enc, 0, true, tid);
        __syncthreads();
    }
    // ---- opp encoder: [18->32->576]
    layer1<18>(s_obs, 30, opp_W1 + p * 576, opp_b1 + p * 32, s_t, 0, tid);
    __syncthreads();
    layer2(s_t, opp_W2 + p * 32 * 576, opp_b2 + p * 576, 576, 576, s_enc, 0, true, tid);
    // stage pi constants into s_obs (obs dead; layer2 does not touch s_obs)
    for (int i = tid; i < 256; i += NT) s_obs[i] = __ldg(pi_b1 + p * 256 + i);
    for (int i = tid; i < 256; i += NT) s_obs[256 + i] = __ldg(pi_b2 + p * 256 + i);
    for (int i = tid; i < 768; i += NT) s_obs[512 + i] = __ldg(pi_W3 + p * 768 + i);
    if (tid < 3) s_obs[1280 + tid] = __ldg(pi_b3 + p * 3 + tid);

    // ---- pi1: enc[64][576] @ W1 -> h1 at enc base (alias-safe)
    pi_gemm(s_enc, ENC_LD, 576, &g_B1h[p][0][0], &g_B1l[p][0][0],
            s_obs, s_enc, H_LD, smc, sbase, tid);
    // ---- pi2: h1[64][260] @ W2 -> h2 at enc+16640
    pi_gemm(s_enc, H_LD, 256, &g_B2h[p][0][0], &g_B2l[p][0][0],
            s_obs + 256, s_enc + 16640, H_LD, smc, sbase, tid);

    // ---- pi3 + tanh
    if (tid < 192) {
        int row = tid / 3, o = tid - row * 3;
        const float* h2 = s_enc + 16640 + row * H_LD;
        float acc = s_obs[1280 + o];
#pragma unroll 8
        for (int k = 0; k < 256; ++k)
            acc = fmaf(h2[k], s_obs[512 + k * 3 + o], acc);
        out[((long)(row0 + row) * 3 + p) * 3 + o] = tanhf(acc);
    }
}

extern "C" void kernel_launch(void* const* d_in, const int* in_sizes, int n_in,
                              void* d_out, int out_size) {
    const float* obs = (const float*)d_in[0];
    const float* prop_W1 = (const float*)d_in[1];
    const float* prop_b1 = (const float*)d_in[2];
    const float* prop_W2 = (const float*)d_in[3];
    const float* prop_b2 = (const float*)d_in[4];
    const float* ext_W1 = (const float*)d_in[5];
    const float* ext_b1 = (const float*)d_in[6];
    const float* ext_W2 = (const float*)d_in[7];
    const float* ext_b2 = (const float*)d_in[8];
    const float* opp_W1 = (const float*)d_in[9];
    const float* opp_b1 = (const float*)d_in[10];
    const float* opp_W2 = (const float*)d_in[11];
    const float* opp_b2 = (const float*)d_in[12];
    const float* pi_W1 = (const float*)d_in[13];
    const float* pi_b1 = (const float*)d_in[14];
    const float* pi_W2 = (const float*)d_in[15];
    const float* pi_b2 = (const float*)d_in[16];
    const float* pi_W3 = (const float*)d_in[17];
    const float* pi_b3 = (const float*)d_in[18];
    float* out = (float*)d_out;

    prep_kernel<<<1728, 256>>>(pi_W1, pi_W2);

    cudaFuncSetAttribute(mlpac_kernel, cudaFuncAttributeMaxDynamicSharedMemorySize, SMEM_B);
    dim3 grid(65536 / TM, 3, 1);
    mlpac_kernel<<<grid, NT, SMEM_B>>>(
        obs, prop_W1, prop_b1, prop_W2, prop_b2, ext_W1, ext_b1, ext_W2, ext_b2,
        opp_W1, opp_b1, opp_W2, opp_b2, pi_W1, pi_b1, pi_W2, pi_b2, pi_W3, pi_b3,
        out);
}

// round 8
// speedup vs baseline: 3.0308x; 1.2231x over previous
#include <cuda_runtime.h>
#include <cuda_bf16.h>
#include <math.h>
#include <stdint.h>

#define TM 64
#define NT 512
#define OBS_LD 52
#define ENC_LD 580
#define H_LD 260

// ---- byte offsets in dynamic smem ----
// [0, 148480)            enc [64][580] fp32
// encoder phase:
#define AENC_H 148480   // 4 A slots x [64][32] bf16 hi (4KB each)
#define AENC_L 164864   // lo
#define BENC_H 181248   // 4 B slots x [32][32] bf16 hi (2KB each)
#define BENC_L 189440   // lo
#define OBS2_B 197632   // obs [64][52] fp32 (13312B)
#define BIAS_B 210944   // enc layer2 biases, 1728 floats (6912B)
#define CNST_B 217856   // pi consts: b1(256) b2(256) W3(768) b3(3) floats
// pi phase (reuses encoder A/B/obs region):
#define A_HI_B 148480
#define A_LO_B 152576
#define B_HI_B 156672
#define B_LO_B 173056
#define SMEM_B 223040

typedef unsigned long long u64;
typedef unsigned int u32;

__device__ __align__(16) __nv_bfloat16 g_B1h[3][256][576];
__device__ __align__(16) __nv_bfloat16 g_B1l[3][256][576];
__device__ __align__(16) __nv_bfloat16 g_B2h[3][256][256];
__device__ __align__(16) __nv_bfloat16 g_B2l[3][256][256];
__device__ __align__(16) __nv_bfloat16 g_eBh[3 * 54 * 1024];  // [p][tile][n32][k32]
__device__ __align__(16) __nv_bfloat16 g_eBl[3 * 54 * 1024];

__device__ __forceinline__ float lrelu(float x) { return fmaxf(x, 0.01f * x); }
__device__ __forceinline__ u32 smem_u32(const void* p) {
    u32 a;
    asm("{ .reg .u64 t; cvta.to.shared.u64 t, %1; cvt.u32.u64 %0, t; }" : "=r"(a) : "l"(p));
    return a;
}
__device__ __forceinline__ u32 pkbf(__nv_bfloat16 a, __nv_bfloat16 b) {
    __nv_bfloat162 t(a, b);
    return *(u32*)&t;
}
// swizzled byte offset: rows of 64B, unit u in 0..3 (16B units)
__device__ __forceinline__ u32 swa(u32 base, int row, int u) {
    return base + row * 64 + ((u ^ ((row >> 1) & 3)) << 4);
}
__device__ __forceinline__ void ldm_x4(u32* r, u32 addr) {
    asm volatile("ldmatrix.sync.aligned.m8n8.x4.shared.b16 {%0,%1,%2,%3}, [%4];"
                 : "=r"(r[0]), "=r"(r[1]), "=r"(r[2]), "=r"(r[3]) : "r"(addr));
}
__device__ __forceinline__ void mma16816(float* d, const u32* a, u32 b0, u32 b1) {
    asm volatile(
        "mma.sync.aligned.m16n8k16.row.col.f32.bf16.bf16.f32 "
        "{%0,%1,%2,%3}, {%4,%5,%6,%7}, {%8,%9}, {%0,%1,%2,%3};"
        : "+f"(d[0]), "+f"(d[1]), "+f"(d[2]), "+f"(d[3])
        : "r"(a[0]), "r"(a[1]), "r"(a[2]), "r"(a[3]), "r"(b0), "r"(b1));
}
__device__ __forceinline__ void split8(const float* x, uint4& hi, uint4& lo) {
    u32 hw[4], lw[4];
#pragma unroll
    for (int j = 0; j < 4; ++j) {
        __nv_bfloat16 h0 = __float2bfloat16(x[2 * j]);
        __nv_bfloat16 h1 = __float2bfloat16(x[2 * j + 1]);
        __nv_bfloat16 l0 = __float2bfloat16(x[2 * j] - __bfloat162float(h0));
        __nv_bfloat16 l1 = __float2bfloat16(x[2 * j + 1] - __bfloat162float(h1));
        hw[j] = pkbf(h0, h1);
        lw[j] = pkbf(l0, l1);
    }
    hi = make_uint4(hw[0], hw[1], hw[2], hw[3]);
    lo = make_uint4(lw[0], lw[1], lw[2], lw[3]);
}

// ---- layer1: [64 rows] x [K->32] + bias + lrelu -> A slot tile (hi/lo bf16)
template <int K>
__device__ __forceinline__ void layer1A(const float* __restrict__ s_obs, int in_off,
                                        const float* __restrict__ W1,
                                        const float* __restrict__ b1,
                                        int slot, char* smc, int tid) {
    const int row = tid & 63;
    const int o0 = (tid >> 6) * 4;
    const float* x = s_obs + row * OBS_LD + in_off;
    float4 b = __ldg((const float4*)(b1 + o0));
    float acc[4] = {b.x, b.y, b.z, b.w};
#pragma unroll
    for (int k = 0; k < K; ++k) {
        float xv = x[k];
        float4 w = __ldg((const float4*)(W1 + k * 32 + o0));
        acc[0] = fmaf(xv, w.x, acc[0]);
        acc[1] = fmaf(xv, w.y, acc[1]);
        acc[2] = fmaf(xv, w.z, acc[2]);
        acc[3] = fmaf(xv, w.w, acc[3]);
    }
    u32 hw[2], lw[2];
#pragma unroll
    for (int j = 0; j < 2; ++j) {
        float v0 = lrelu(acc[2 * j]), v1 = lrelu(acc[2 * j + 1]);
        __nv_bfloat16 h0 = __float2bfloat16(v0);
        __nv_bfloat16 h1 = __float2bfloat16(v1);
        __nv_bfloat16 l0 = __float2bfloat16(v0 - __bfloat162float(h0));
        __nv_bfloat16 l1 = __float2bfloat16(v1 - __bfloat162float(h1));
        hw[j] = pkbf(h0, h1);
        lw[j] = pkbf(l0, l1);
    }
    u32 off = swa(0, row, o0 >> 3) + ((o0 & 4) << 1);
    *(uint2*)(smc + AENC_H + slot * 4096 + off) = make_uint2(hw[0], hw[1]);
    *(uint2*)(smc + AENC_L + slot * 4096 + off) = make_uint2(lw[0], lw[1]);
}

// ======================= HMMA pi GEMM (R7, unchanged) =======================
__device__ void pi_gemm(const float* __restrict__ sA, int lda, int Kt,
                        const __nv_bfloat16* __restrict__ Bh,
                        const __nv_bfloat16* __restrict__ Bl,
                        const float* __restrict__ sBias,
                        float* __restrict__ sOut, int ldo,
                        char* smc, u32 sbase, int tid) {
    const int w = tid >> 5, lane = tid & 31;
    const int m0w = (w & 1) * 32;
    const int n0w = (w >> 1) * 32;
    const int fr = ((lane >> 3) & 1) * 8 + (lane & 7);
    const int fu = lane >> 4;

    u32 adAh[2][2], adAl[2][2], adBh[2][2], adBl[2][2];
#pragma unroll
    for (int ks = 0; ks < 2; ++ks) {
        int ua = ks * 2 + fu;
#pragma unroll
        for (int t = 0; t < 2; ++t) {
            int rm = m0w + t * 16 + fr;
            int rn = n0w + t * 16 + fr;
            adAh[ks][t] = sbase + swa(A_HI_B, rm, ua);
            adAl[ks][t] = sbase + swa(A_LO_B, rm, ua);
            adBh[ks][t] = sbase + swa(B_HI_B, rn, ua);
            adBl[ks][t] = sbase + swa(B_LO_B, rn, ua);
        }
    }
    const int crow = tid >> 2, cu = tid & 3;
    const u32 stAh = sbase + swa(A_HI_B, crow & 63, cu);
    const u32 stAl = sbase + swa(A_LO_B, crow & 63, cu);
    const float* asrc = sA + (crow & 63) * lda + cu * 8;
    const int br0 = tid >> 2, bu0 = tid & 3;
    const int br1 = (tid + 512) >> 2, bu1 = tid & 3;
    const u32 stBh0 = sbase + swa(B_HI_B, br0, bu0);
    const u32 stBl0 = sbase + swa(B_LO_B, br0, bu0);
    const u32 stBh1 = sbase + swa(B_HI_B, br1, bu1);
    const u32 stBl1 = sbase + swa(B_LO_B, br1, bu1);
    const __nv_bfloat16* bsrcH0 = Bh + (long)br0 * Kt + bu0 * 8;
    const __nv_bfloat16* bsrcL0 = Bl + (long)br0 * Kt + bu0 * 8;
    const __nv_bfloat16* bsrcH1 = Bh + (long)br1 * Kt + bu1 * 8;
    const __nv_bfloat16* bsrcL1 = Bl + (long)br1 * Kt + bu1 * 8;

    float d[2][4][4];
#pragma unroll
    for (int i = 0; i < 2; ++i)
#pragma unroll
        for (int j = 0; j < 4; ++j)
#pragma unroll
            for (int q = 0; q < 4; ++q) d[i][j][q] = 0.f;

    const int NCh = Kt >> 5;
    __syncthreads();

    uint4 pBh0 = *(const uint4*)(bsrcH0);
    uint4 pBl0 = *(const uint4*)(bsrcL0);
    uint4 pBh1 = *(const uint4*)(bsrcH1);
    uint4 pBl1 = *(const uint4*)(bsrcL1);
    float4 pA0, pA1;
    if (tid < 256) { pA0 = *(const float4*)asrc; pA1 = *(const float4*)(asrc + 4); }

    for (int kc = 0; kc < NCh; ++kc) {
        __syncthreads();
        if (tid < 256) {
            float x[8] = {pA0.x, pA0.y, pA0.z, pA0.w, pA1.x, pA1.y, pA1.z, pA1.w};
            uint4 hi, lo;
            split8(x, hi, lo);
            *(uint4*)(smc + (stAh - sbase)) = hi;
            *(uint4*)(smc + (stAl - sbase)) = lo;
        }
        *(uint4*)(smc + (stBh0 - sbase)) = pBh0;
        *(uint4*)(smc + (stBl0 - sbase)) = pBl0;
        *(uint4*)(smc + (stBh1 - sbase)) = pBh1;
        *(uint4*)(smc + (stBl1 - sbase)) = pBl1;
        __syncthreads();
        if (kc + 1 < NCh) {
            int ko = (kc + 1) * 32;
            pBh0 = *(const uint4*)(bsrcH0 + ko);
            pBl0 = *(const uint4*)(bsrcL0 + ko);
            pBh1 = *(const uint4*)(bsrcH1 + ko);
            pBl1 = *(const uint4*)(bsrcL1 + ko);
            if (tid < 256) {
                pA0 = *(const float4*)(asrc + ko);
                pA1 = *(const float4*)(asrc + ko + 4);
            }
        }
#pragma unroll
        for (int ks = 0; ks < 2; ++ks) {
            u32 ah[2][4], al[2][4], bh[2][4], bl[2][4];
#pragma unroll
            for (int t = 0; t < 2; ++t) {
                ldm_x4(ah[t], adAh[ks][t]);
                ldm_x4(al[t], adAl[ks][t]);
                ldm_x4(bh[t], adBh[ks][t]);
                ldm_x4(bl[t], adBl[ks][t]);
            }
#pragma unroll
            for (int mt = 0; mt < 2; ++mt)
#pragma unroll
                for (int nt = 0; nt < 4; ++nt) {
                    int nh = nt >> 1, hf = nt & 1;
                    mma16816(d[mt][nt], ah[mt], bh[nh][hf], bh[nh][2 + hf]);
                    mma16816(d[mt][nt], ah[mt], bl[nh][hf], bl[nh][2 + hf]);
                    mma16816(d[mt][nt], al[mt], bh[nh][hf], bh[nh][2 + hf]);
                }
        }
    }
    __syncthreads();
#pragma unroll
    for (int mt = 0; mt < 2; ++mt)
#pragma unroll
        for (int nt = 0; nt < 4; ++nt) {
            int col = n0w + nt * 8 + (lane & 3) * 2;
            int row = m0w + mt * 16 + (lane >> 2);
            float2 b = *(const float2*)(sBias + col);
            *(float2*)(sOut + row * ldo + col) =
                make_float2(lrelu(d[mt][nt][0] + b.x), lrelu(d[mt][nt][1] + b.y));
            *(float2*)(sOut + (row + 8) * ldo + col) =
                make_float2(lrelu(d[mt][nt][2] + b.x), lrelu(d[mt][nt][3] + b.y));
        }
    __syncthreads();
}

// ======================= prep ===============================================
__global__ void prep_kernel(const float* __restrict__ W1, const float* __restrict__ W2,
                            const float* __restrict__ pW2, const float* __restrict__ eW2,
                            const float* __restrict__ oW2) {
    int i = blockIdx.x * 256 + threadIdx.x;
    if (i < 3 * 576 * 256) {
        int p = i / (576 * 256), rem = i % (576 * 256);
        int k = rem / 256, n = rem % 256;
        float w = __ldg(W1 + i);
        __nv_bfloat16 h = __float2bfloat16(w);
        g_B1h[p][n][k] = h;
        g_B1l[p][n][k] = __float2bfloat16(w - __bfloat162float(h));
    }
    if (i < 3 * 256 * 256) {
        int p = i / (256 * 256), rem = i % (256 * 256);
        int k = rem / 256, n = rem % 256;
        float w = __ldg(W2 + i);
        __nv_bfloat16 h = __float2bfloat16(w);
        g_B2h[p][n][k] = h;
        g_B2l[p][n][k] = __float2bfloat16(w - __bfloat162float(h));
    }
    if (i < 3 * 54 * 1024) {
        int p = i / (54 * 1024), rem = i % (54 * 1024);
        int t = rem / 1024, nk = rem % 1024;
        int n = nk / 32, k = nk % 32;
        float w;
        if (t < 18) {
            int s = t >> 1;
            w = __ldg(pW2 + ((p * 9 + s) * 32 + k) * 64 + (t & 1) * 32 + n);
        } else if (t < 36) {
            int e = (t - 18) / 9, tt = (t - 18) % 9;
            w = __ldg(eW2 + ((p * 2 + e) * 32 + k) * 288 + tt * 32 + n);
        } else {
            w = __ldg(oW2 + (p * 32 + k) * 576 + (t - 36) * 32 + n);
        }
        __nv_bfloat16 h = __float2bfloat16(w);
        g_eBh[i] = h;
        g_eBl[i] = __float2bfloat16(w - __bfloat162float(h));
    }
}

// ======================= fused kernel =======================================
__global__ void __launch_bounds__(NT, 1)
mlpac_kernel(const float* __restrict__ obs,
             const float* __restrict__ prop_W1, const float* __restrict__ prop_b1,
             const float* __restrict__ prop_W2, const float* __restrict__ prop_b2,
             const float* __restrict__ ext_W1, const float* __restrict__ ext_b1,
             const float* __restrict__ ext_W2, const float* __restrict__ ext_b2,
             const float* __restrict__ opp_W1, const float* __restrict__ opp_b1,
             const float* __restrict__ opp_W2, const float* __restrict__ opp_b2,
             const float* __restrict__ pi_W1, const float* __restrict__ pi_b1,
             const float* __restrict__ pi_W2, const float* __restrict__ pi_b2,
             const float* __restrict__ pi_W3, const float* __restrict__ pi_b3,
             float* __restrict__ out) {
    extern __shared__ float sm[];
    char* smc = (char*)sm;
    float* s_enc = sm;
    float* s_obs = sm + OBS2_B / 4;
    float* bias_sm = sm + BIAS_B / 4;   // 1728 floats
    float* cst = sm + CNST_B / 4;       // pi consts
    u32 sbase = smem_u32(sm);

    const int tid = threadIdx.x;
    const int p = blockIdx.y;
    const int row0 = blockIdx.x * TM;

    // obs tile + bias/const staging
    for (int idx = tid; idx < TM * 12; idx += NT) {
        int r = idx / 12, c = (idx % 12) * 4;
        const float* src = obs + ((long)(row0 + r) * 3 + p) * 48 + c;
        *((float4*)(s_obs + r * OBS_LD + c)) = __ldg((const float4*)src);
    }
    for (int i = tid; i < 576; i += NT) {
        bias_sm[i] = __ldg(prop_b2 + p * 576 + i);
        bias_sm[576 + i] = __ldg(ext_b2 + p * 576 + i);
        bias_sm[1152 + i] = __ldg(opp_b2 + p * 576 + i);
    }
    for (int i = tid; i < 256; i += NT) cst[i] = __ldg(pi_b1 + p * 256 + i);
    for (int i = tid; i < 256; i += NT) cst[256 + i] = __ldg(pi_b2 + p * 256 + i);
    for (int i = tid; i < 768; i += NT) cst[512 + i] = __ldg(pi_W3 + p * 768 + i);
    if (tid < 3) cst[1280 + tid] = __ldg(pi_b3 + p * 3 + tid);
    __syncthreads();

    // ======== encoder: 14 HMMA sweeps over 54 n32-tiles ========
    for (int sweep = 0; sweep < 14; ++sweep) {
        if (sweep == 0) {
#pragma unroll
            for (int s = 0; s < 4; ++s)
                layer1A<2>(s_obs, 2 * s, prop_W1 + p * 576 + s * 64,
                           prop_b1 + p * 288 + s * 32, s, smc, tid);
        } else if (sweep == 2) {
#pragma unroll
            for (int s = 0; s < 4; ++s)
                layer1A<2>(s_obs, 2 * (4 + s), prop_W1 + p * 576 + (4 + s) * 64,
                           prop_b1 + p * 288 + (4 + s) * 32, s, smc, tid);
        } else if (sweep == 4) {
            layer1A<2>(s_obs, 16, prop_W1 + p * 576 + 512, prop_b1 + p * 288 + 256, 0, smc, tid);
            layer1A<6>(s_obs, 18, ext_W1 + p * 384, ext_b1 + p * 64, 1, smc, tid);
            layer1A<6>(s_obs, 24, ext_W1 + p * 384 + 192, ext_b1 + p * 64 + 32, 2, smc, tid);
            layer1A<18>(s_obs, 30, opp_W1 + p * 576, opp_b1 + p * 32, 3, smc, tid);
        }
        // stage 4 B tiles
        {
            int slot = tid >> 7, r = (tid >> 2) & 31, u = tid & 3;
            int tile = sweep * 4 + slot;
            if (tile < 54) {
                long so = ((long)(p * 54 + tile) * 32 + r) * 32 + u * 8;
                uint4 hv = *(const uint4*)(g_eBh + so);
                uint4 lv = *(const uint4*)(g_eBl + so);
                *(uint4*)(smc + swa(BENC_H + slot * 2048, r, u)) = hv;
                *(uint4*)(smc + swa(BENC_L + slot * 2048, r, u)) = lv;
            }
        }
        __syncthreads();
        // gemm: warp -> m16 x n32 of one tile
        {
            int w = tid >> 5, lane = tid & 31;
            int m0 = (w & 3) * 16, slot = w >> 2;
            int tile = sweep * 4 + slot;
            if (tile < 54) {
                int asl = (tile < 16) ? ((tile >> 1) & 3)
                                      : (tile < 18 ? 0 : (tile < 27 ? 1 : (tile < 36 ? 2 : 3)));
                int ecol = (tile < 18) ? tile * 32
                          : (tile < 27 ? (tile - 18) * 32
                          : (tile < 36 ? 288 + (tile - 27) * 32 : (tile - 36) * 32));
                bool addm = tile >= 18;
                int fr = ((lane >> 3) & 1) * 8 + (lane & 7), fu = lane >> 4;
                float d[4][4];
#pragma unroll
                for (int j = 0; j < 4; ++j)
#pragma unroll
                    for (int q = 0; q < 4; ++q) d[j][q] = 0.f;
#pragma unroll
                for (int ks = 0; ks < 2; ++ks) {
                    int ua = ks * 2 + fu;
                    u32 ah[4], al[4], bh[2][4], bl[2][4];
                    ldm_x4(ah, sbase + swa(AENC_H + asl * 4096, m0 + fr, ua));
                    ldm_x4(al, sbase + swa(AENC_L + asl * 4096, m0 + fr, ua));
                    ldm_x4(bh[0], sbase + swa(BENC_H + slot * 2048, fr, ua));
                    ldm_x4(bh[1], sbase + swa(BENC_H + slot * 2048, 16 + fr, ua));
                    ldm_x4(bl[0], sbase + swa(BENC_L + slot * 2048, fr, ua));
                    ldm_x4(bl[1], sbase + swa(BENC_L + slot * 2048, 16 + fr, ua));
#pragma unroll
                    for (int nt = 0; nt < 4; ++nt) {
                        int nh = nt >> 1, hf = nt & 1;
                        mma16816(d[nt], ah, bh[nh][hf], bh[nh][2 + hf]);
                        mma16816(d[nt], ah, bl[nh][hf], bl[nh][2 + hf]);
                        mma16816(d[nt], al, bh[nh][hf], bh[nh][2 + hf]);
                    }
                }
#pragma unroll
                for (int nt = 0; nt < 4; ++nt) {
                    int col = ecol + nt * 8 + (lane & 3) * 2;
                    int r0 = m0 + (lane >> 2);
                    float2 b = *(const float2*)(bias_sm + tile * 32 + nt * 8 + (lane & 3) * 2);
                    float2 v0 = make_float2(lrelu(d[nt][0] + b.x), lrelu(d[nt][1] + b.y));
                    float2 v1 = make_float2(lrelu(d[nt][2] + b.x), lrelu(d[nt][3] + b.y));
                    float* e0 = s_enc + r0 * ENC_LD + col;
                    float* e1 = e0 + 8 * ENC_LD;
                    if (addm) {
                        float2 o0 = *(float2*)e0, o1 = *(float2*)e1;
                        v0.x += o0.x; v0.y += o0.y; v1.x += o1.x; v1.y += o1.y;
                    }
                    *(float2*)e0 = v0;
                    *(float2*)e1 = v1;
                }
            }
        }
        __syncthreads();
    }

    // ======== pi MLP ========
    pi_gemm(s_enc, ENC_LD, 576, &g_B1h[p][0][0], &g_B1l[p][0][0],
            cst, s_enc, H_LD, smc, sbase, tid);
    pi_gemm(s_enc, H_LD, 256, &g_B2h[p][0][0], &g_B2l[p][0][0],
            cst + 256, s_enc + 16640, H_LD, smc, sbase, tid);

    if (tid < 192) {
        int row = tid / 3, o = tid - row * 3;
        const float* h2 = s_enc + 16640 + row * H_LD;
        float acc = cst[1280 + o];
#pragma unroll 8
        for (int k = 0; k < 256; ++k)
            acc = fmaf(h2[k], cst[512 + k * 3 + o], acc);
        out[((long)(row0 + row) * 3 + p) * 3 + o] = tanhf(acc);
    }
}

extern "C" void kernel_launch(void* const* d_in, const int* in_sizes, int n_in,
                              void* d_out, int out_size) {
    const float* obs = (const float*)d_in[0];
    const float* prop_W1 = (const float*)d_in[1];
    const float* prop_b1 = (const float*)d_in[2];
    const float* prop_W2 = (const float*)d_in[3];
    const float* prop_b2 = (const float*)d_in[4];
    const float* ext_W1 = (const float*)d_in[5];
    const float* ext_b1 = (const float*)d_in[6];
    const float* ext_W2 = (const float*)d_in[7];
    const float* ext_b2 = (const float*)d_in[8];
    const float* opp_W1 = (const float*)d_in[9];
    const float* opp_b1 = (const float*)d_in[10];
    const float* opp_W2 = (const float*)d_in[11];
    const float* opp_b2 = (const float*)d_in[12];
    const float* pi_W1 = (const float*)d_in[13];
    const float* pi_b1 = (const float*)d_in[14];
    const float* pi_W2 = (const float*)d_in[15];
    const float* pi_b2 = (const float*)d_in[16];
    const float* pi_W3 = (const float*)d_in[17];
    const float* pi_b3 = (const float*)d_in[18];
    float* out = (float*)d_out;

    prep_kernel<<<1728, 256>>>(pi_W1, pi_W2, prop_W2, ext_W2, opp_W2);

    cudaFuncSetAttribute(mlpac_kernel, cudaFuncAttributeMaxDynamicSharedMemorySize, SMEM_B);
    dim3 grid(65536 / TM, 3, 1);
    mlpac_kernel<<<grid, NT, SMEM_B>>>(
        obs, prop_W1, prop_b1, prop_W2, prop_b2, ext_W1, ext_b1, ext_W2, ext_b2,
        opp_W1, opp_b1, opp_W2, opp_b2, pi_W1, pi_b1, pi_W2, pi_b2, pi_W3, pi_b3,
        out);
}

// round 9
// speedup vs baseline: 3.1774x; 1.0484x over previous
#include <cuda_runtime.h>
#include <cuda_bf16.h>
#include <math.h>
#include <stdint.h>

#define TM 64
#define NT 512
#define OBS_LD 52
#define ENC_LD 580
#define H_LD 260

// ---- byte offsets in dynamic smem ----
// [0, 148480)  enc [64][580] fp32 (encoder + pi1 A); later: h1 tiles + h2
#define H1T_H 0         // 8 h1 tiles x [64][32] bf16 hi (4KB each)
#define H1T_L 32768     // lo
#define H2_B  65536     // h2 fp32 [64][260] (66560B, ends 132096)
// encoder phase:
#define AENC_H 148480   // 4 A slots x [64][32] bf16 hi (4KB each)
#define AENC_L 164864   // lo
#define BENC_H 181248   // 4 B slots x [32][32] bf16 hi (2KB each)
#define BENC_L 189440   // lo
#define OBS2_B 197632   // obs [64][52] fp32
#define BIAS_B 210944   // enc layer2 biases, 1728 floats
#define CNST_B 217856   // pi consts: b1(256) b2(256) W3(768) b3(3)
// pi phase (reuses encoder A/B region):
#define A_HI_B 148480
#define A_LO_B 152576
#define B_HI_B 156672
#define B_LO_B 173056
#define SMEM_B 223040

typedef unsigned long long u64;
typedef unsigned int u32;

__device__ __align__(16) __nv_bfloat16 g_B1h[3][256][576];
__device__ __align__(16) __nv_bfloat16 g_B1l[3][256][576];
__device__ __align__(16) __nv_bfloat16 g_B2h[3][256][256];
__device__ __align__(16) __nv_bfloat16 g_B2l[3][256][256];
__device__ __align__(16) __nv_bfloat16 g_eBh[3 * 54 * 1024];
__device__ __align__(16) __nv_bfloat16 g_eBl[3 * 54 * 1024];

__device__ __forceinline__ float lrelu(float x) { return fmaxf(x, 0.01f * x); }
__device__ __forceinline__ u32 smem_u32(const void* p) {
    u32 a;
    asm("{ .reg .u64 t; cvta.to.shared.u64 t, %1; cvt.u32.u64 %0, t; }" : "=r"(a) : "l"(p));
    return a;
}
__device__ __forceinline__ u32 pkbf(__nv_bfloat16 a, __nv_bfloat16 b) {
    __nv_bfloat162 t(a, b);
    return *(u32*)&t;
}
__device__ __forceinline__ u32 swa(u32 base, int row, int u) {
    return base + row * 64 + ((u ^ ((row >> 1) & 3)) << 4);
}
__device__ __forceinline__ void ldm_x4(u32* r, u32 addr) {
    asm volatile("ldmatrix.sync.aligned.m8n8.x4.shared.b16 {%0,%1,%2,%3}, [%4];"
                 : "=r"(r[0]), "=r"(r[1]), "=r"(r[2]), "=r"(r[3]) : "r"(addr));
}
__device__ __forceinline__ void mma16816(float* d, const u32* a, u32 b0, u32 b1) {
    asm volatile(
        "mma.sync.aligned.m16n8k16.row.col.f32.bf16.bf16.f32 "
        "{%0,%1,%2,%3}, {%4,%5,%6,%7}, {%8,%9}, {%0,%1,%2,%3};"
        : "+f"(d[0]), "+f"(d[1]), "+f"(d[2]), "+f"(d[3])
        : "r"(a[0]), "r"(a[1]), "r"(a[2]), "r"(a[3]), "r"(b0), "r"(b1));
}
__device__ __forceinline__ void split8(const float* x, uint4& hi, uint4& lo) {
    u32 hw[4], lw[4];
#pragma unroll
    for (int j = 0; j < 4; ++j) {
        __nv_bfloat16 h0 = __float2bfloat16(x[2 * j]);
        __nv_bfloat16 h1 = __float2bfloat16(x[2 * j + 1]);
        __nv_bfloat16 l0 = __float2bfloat16(x[2 * j] - __bfloat162float(h0));
        __nv_bfloat16 l1 = __float2bfloat16(x[2 * j + 1] - __bfloat162float(h1));
        hw[j] = pkbf(h0, h1);
        lw[j] = pkbf(l0, l1);
    }
    hi = make_uint4(hw[0], hw[1], hw[2], hw[3]);
    lo = make_uint4(lw[0], lw[1], lw[2], lw[3]);
}
__device__ __forceinline__ void split2(float v0, float v1, u32& hi, u32& lo) {
    __nv_bfloat16 h0 = __float2bfloat16(v0);
    __nv_bfloat16 h1 = __float2bfloat16(v1);
    hi = pkbf(h0, h1);
    lo = pkbf(__float2bfloat16(v0 - __bfloat162float(h0)),
              __float2bfloat16(v1 - __bfloat162float(h1)));
}

// ---- layer1: [64 rows] x [K->32] + bias + lrelu -> A slot tile (hi/lo bf16)
template <int K>
__device__ __forceinline__ void layer1A(const float* __restrict__ s_obs, int in_off,
                                        const float* __restrict__ W1,
                                        const float* __restrict__ b1,
                                        int slot, char* smc, int tid) {
    const int row = tid & 63;
    const int o0 = (tid >> 6) * 4;
    const float* x = s_obs + row * OBS_LD + in_off;
    float4 b = __ldg((const float4*)(b1 + o0));
    float acc[4] = {b.x, b.y, b.z, b.w};
#pragma unroll
    for (int k = 0; k < K; ++k) {
        float xv = x[k];
        float4 w = __ldg((const float4*)(W1 + k * 32 + o0));
        acc[0] = fmaf(xv, w.x, acc[0]);
        acc[1] = fmaf(xv, w.y, acc[1]);
        acc[2] = fmaf(xv, w.z, acc[2]);
        acc[3] = fmaf(xv, w.w, acc[3]);
    }
    u32 hw[2], lw[2];
    split2(lrelu(acc[0]), lrelu(acc[1]), hw[0], lw[0]);
    split2(lrelu(acc[2]), lrelu(acc[3]), hw[1], lw[1]);
    u32 off = swa(0, row, o0 >> 3) + ((o0 & 4) << 1);
    *(uint2*)(smc + AENC_H + slot * 4096 + off) = make_uint2(hw[0], hw[1]);
    *(uint2*)(smc + AENC_L + slot * 4096 + off) = make_uint2(lw[0], lw[1]);
}

// ======================= HMMA pi GEMM =======================================
// AT=false: A converted from fp32 sA (prefetched). AT=true: A read in place
// from pre-built hi/lo tiles at aTH/aTL (+4KB per chunk).
// OT=false: fp32 out to sOut. OT=true: out written as hi/lo tiles at oTH/oTL.
template <bool AT, bool OT>
__device__ void pi_gemm(const float* __restrict__ sA, int lda, int Kt,
                        const __nv_bfloat16* __restrict__ Bh,
                        const __nv_bfloat16* __restrict__ Bl,
                        const float* __restrict__ sBias,
                        float* __restrict__ sOut, int ldo,
                        u32 aTH, u32 aTL, u32 oTH, u32 oTL,
                        char* smc, u32 sbase, int tid) {
    const int w = tid >> 5, lane = tid & 31;
    const int m0w = (w & 1) * 32;
    const int n0w = (w >> 1) * 32;
    const int fr = ((lane >> 3) & 1) * 8 + (lane & 7);
    const int fu = lane >> 4;

    // ldmatrix offsets; for AT these are relative (chunk adds kc*4096)
    u32 adAh[2][2], adAl[2][2], adBh[2][2], adBl[2][2];
#pragma unroll
    for (int ks = 0; ks < 2; ++ks) {
        int ua = ks * 2 + fu;
#pragma unroll
        for (int t = 0; t < 2; ++t) {
            int rm = m0w + t * 16 + fr;
            int rn = n0w + t * 16 + fr;
            if (AT) {
                adAh[ks][t] = sbase + swa(aTH, rm, ua);
                adAl[ks][t] = sbase + swa(aTL, rm, ua);
            } else {
                adAh[ks][t] = sbase + swa(A_HI_B, rm, ua);
                adAl[ks][t] = sbase + swa(A_LO_B, rm, ua);
            }
            adBh[ks][t] = sbase + swa(B_HI_B, rn, ua);
            adBl[ks][t] = sbase + swa(B_LO_B, rn, ua);
        }
    }
    const int crow = tid >> 2, cu = tid & 3;
    const u32 stAh = sbase + swa(A_HI_B, crow & 63, cu);
    const u32 stAl = sbase + swa(A_LO_B, crow & 63, cu);
    const float* asrc = sA + (crow & 63) * lda + cu * 8;
    const int br0 = tid >> 2;
    const int br1 = (tid + 512) >> 2;
    const u32 stBh0 = sbase + swa(B_HI_B, br0, cu);
    const u32 stBl0 = sbase + swa(B_LO_B, br0, cu);
    const u32 stBh1 = sbase + swa(B_HI_B, br1, cu);
    const u32 stBl1 = sbase + swa(B_LO_B, br1, cu);
    const __nv_bfloat16* bsrcH0 = Bh + (long)br0 * Kt + cu * 8;
    const __nv_bfloat16* bsrcL0 = Bl + (long)br0 * Kt + cu * 8;
    const __nv_bfloat16* bsrcH1 = Bh + (long)br1 * Kt + cu * 8;
    const __nv_bfloat16* bsrcL1 = Bl + (long)br1 * Kt + cu * 8;

    float d[2][4][4];
#pragma unroll
    for (int i = 0; i < 2; ++i)
#pragma unroll
        for (int j = 0; j < 4; ++j)
#pragma unroll
            for (int q = 0; q < 4; ++q) d[i][j][q] = 0.f;

    const int NCh = Kt >> 5;
    __syncthreads();

    uint4 pBh0 = *(const uint4*)(bsrcH0);
    uint4 pBl0 = *(const uint4*)(bsrcL0);
    uint4 pBh1 = *(const uint4*)(bsrcH1);
    uint4 pBl1 = *(const uint4*)(bsrcL1);
    float4 pA0, pA1;
    if (!AT && tid < 256) { pA0 = *(const float4*)asrc; pA1 = *(const float4*)(asrc + 4); }

    for (int kc = 0; kc < NCh; ++kc) {
        __syncthreads();
        if (!AT && tid < 256) {
            float x[8] = {pA0.x, pA0.y, pA0.z, pA0.w, pA1.x, pA1.y, pA1.z, pA1.w};
            uint4 hi, lo;
            split8(x, hi, lo);
            *(uint4*)(smc + (stAh - sbase)) = hi;
            *(uint4*)(smc + (stAl - sbase)) = lo;
        }
        *(uint4*)(smc + (stBh0 - sbase)) = pBh0;
        *(uint4*)(smc + (stBl0 - sbase)) = pBl0;
        *(uint4*)(smc + (stBh1 - sbase)) = pBh1;
        *(uint4*)(smc + (stBl1 - sbase)) = pBl1;
        __syncthreads();
        if (kc + 1 < NCh) {
            int ko = (kc + 1) * 32;
            pBh0 = *(const uint4*)(bsrcH0 + ko);
            pBl0 = *(const uint4*)(bsrcL0 + ko);
            pBh1 = *(const uint4*)(bsrcH1 + ko);
            pBl1 = *(const uint4*)(bsrcL1 + ko);
            if (!AT && tid < 256) {
                pA0 = *(const float4*)(asrc + ko);
                pA1 = *(const float4*)(asrc + ko + 4);
            }
        }
        const u32 aoff = AT ? (u32)(kc * 4096) : 0u;
#pragma unroll
        for (int ks = 0; ks < 2; ++ks) {
            u32 ah[2][4], al[2][4], bh[2][4], bl[2][4];
#pragma unroll
            for (int t = 0; t < 2; ++t) {
                ldm_x4(ah[t], adAh[ks][t] + aoff);
                ldm_x4(al[t], adAl[ks][t] + aoff);
                ldm_x4(bh[t], adBh[ks][t]);
                ldm_x4(bl[t], adBl[ks][t]);
            }
#pragma unroll
            for (int mt = 0; mt < 2; ++mt)
#pragma unroll
                for (int nt = 0; nt < 4; ++nt) {
                    int nh = nt >> 1, hf = nt & 1;
                    mma16816(d[mt][nt], ah[mt], bh[nh][hf], bh[nh][2 + hf]);
                    mma16816(d[mt][nt], ah[mt], bl[nh][hf], bl[nh][2 + hf]);
                    mma16816(d[mt][nt], al[mt], bh[nh][hf], bh[nh][2 + hf]);
                }
        }
    }
    __syncthreads();
    // ---- readout
#pragma unroll
    for (int mt = 0; mt < 2; ++mt)
#pragma unroll
        for (int nt = 0; nt < 4; ++nt) {
            int lc = nt * 8 + (lane & 3) * 2;       // col within n32 group
            int col = n0w + lc;
            int row = m0w + mt * 16 + (lane >> 2);
            float2 b = *(const float2*)(sBias + col);
            float v0 = lrelu(d[mt][nt][0] + b.x), v1 = lrelu(d[mt][nt][1] + b.y);
            float v2 = lrelu(d[mt][nt][2] + b.x), v3 = lrelu(d[mt][nt][3] + b.y);
            if (OT) {
                int tile = n0w >> 5;
                u32 off0 = swa((u32)(tile * 4096), row, lc >> 3) + (lc & 7) * 2;
                u32 off1 = swa((u32)(tile * 4096), row + 8, lc >> 3) + (lc & 7) * 2;
                u32 h0, l0, h1, l1;
                split2(v0, v1, h0, l0);
                split2(v2, v3, h1, l1);
                *(u32*)(smc + oTH + off0) = h0;
                *(u32*)(smc + oTL + off0) = l0;
                *(u32*)(smc + oTH + off1) = h1;
                *(u32*)(smc + oTL + off1) = l1;
            } else {
                *(float2*)(sOut + row * ldo + col) = make_float2(v0, v1);
                *(float2*)(sOut + (row + 8) * ldo + col) = make_float2(v2, v3);
            }
        }
    __syncthreads();
}

// ======================= prep ===============================================
__global__ void prep_kernel(const float* __restrict__ W1, const float* __restrict__ W2,
                            const float* __restrict__ pW2, const float* __restrict__ eW2,
                            const float* __restrict__ oW2) {
    int i = blockIdx.x * 256 + threadIdx.x;
    if (i < 3 * 576 * 256) {
        int p = i / (576 * 256), rem = i % (576 * 256);
        int k = rem / 256, n = rem % 256;
        float w = __ldg(W1 + i);
        __nv_bfloat16 h = __float2bfloat16(w);
        g_B1h[p][n][k] = h;
        g_B1l[p][n][k] = __float2bfloat16(w - __bfloat162float(h));
    }
    if (i < 3 * 256 * 256) {
        int p = i / (256 * 256), rem = i % (256 * 256);
        int k = rem / 256, n = rem % 256;
        float w = __ldg(W2 + i);
        __nv_bfloat16 h = __float2bfloat16(w);
        g_B2h[p][n][k] = h;
        g_B2l[p][n][k] = __float2bfloat16(w - __bfloat162float(h));
    }
    if (i < 3 * 54 * 1024) {
        int p = i / (54 * 1024), rem = i % (54 * 1024);
        int t = rem / 1024, nk = rem % 1024;
        int n = nk / 32, k = nk % 32;
        float w;
        if (t < 18) {
            int s = t >> 1;
            w = __ldg(pW2 + ((p * 9 + s) * 32 + k) * 64 + (t & 1) * 32 + n);
        } else if (t < 36) {
            int e = (t - 18) / 9, tt = (t - 18) % 9;
            w = __ldg(eW2 + ((p * 2 + e) * 32 + k) * 288 + tt * 32 + n);
        } else {
            w = __ldg(oW2 + (p * 32 + k) * 576 + (t - 36) * 32 + n);
        }
        __nv_bfloat16 h = __float2bfloat16(w);
        g_eBh[i] = h;
        g_eBl[i] = __float2bfloat16(w - __bfloat162float(h));
    }
}

// ======================= fused kernel =======================================
__global__ void __launch_bounds__(NT, 1)
mlpac_kernel(const float* __restrict__ obs,
             const float* __restrict__ prop_W1, const float* __restrict__ prop_b1,
             const float* __restrict__ prop_W2, const float* __restrict__ prop_b2,
             const float* __restrict__ ext_W1, const float* __restrict__ ext_b1,
             const float* __restrict__ ext_W2, const float* __restrict__ ext_b2,
             const float* __restrict__ opp_W1, const float* __restrict__ opp_b1,
             const float* __restrict__ opp_W2, const float* __restrict__ opp_b2,
             const float* __restrict__ pi_W1, const float* __restrict__ pi_b1,
             const float* __restrict__ pi_W2, const float* __restrict__ pi_b2,
             const float* __restrict__ pi_W3, const float* __restrict__ pi_b3,
             float* __restrict__ out) {
    extern __shared__ float sm[];
    char* smc = (char*)sm;
    float* s_enc = sm;
    float* s_obs = sm + OBS2_B / 4;
    float* bias_sm = sm + BIAS_B / 4;
    float* cst = sm + CNST_B / 4;
    u32 sbase = smem_u32(sm);

    const int tid = threadIdx.x;
    const int p = blockIdx.y;
    const int row0 = blockIdx.x * TM;

    for (int idx = tid; idx < TM * 12; idx += NT) {
        int r = idx / 12, c = (idx % 12) * 4;
        const float* src = obs + ((long)(row0 + r) * 3 + p) * 48 + c;
        *((float4*)(s_obs + r * OBS_LD + c)) = __ldg((const float4*)src);
    }
    for (int i = tid; i < 576; i += NT) {
        bias_sm[i] = __ldg(prop_b2 + p * 576 + i);
        bias_sm[576 + i] = __ldg(ext_b2 + p * 576 + i);
        bias_sm[1152 + i] = __ldg(opp_b2 + p * 576 + i);
    }
    for (int i = tid; i < 256; i += NT) cst[i] = __ldg(pi_b1 + p * 256 + i);
    for (int i = tid; i < 256; i += NT) cst[256 + i] = __ldg(pi_b2 + p * 256 + i);
    for (int i = tid; i < 768; i += NT) cst[512 + i] = __ldg(pi_W3 + p * 768 + i);
    if (tid < 3) cst[1280 + tid] = __ldg(pi_b3 + p * 3 + tid);
    __syncthreads();

    // ======== encoder: 14 HMMA sweeps, B tiles register-prefetched ========
    const int bslot = tid >> 7, brr = (tid >> 2) & 31, bu = tid & 3;
    const u32 stEh = swa((u32)(BENC_H + bslot * 2048), brr, bu);
    const u32 stEl = swa((u32)(BENC_L + bslot * 2048), brr, bu);
    uint4 pEh, pEl;
    {
        int tile = bslot;  // sweep 0
        long so = ((long)(p * 54 + tile) * 32 + brr) * 32 + bu * 8;
        pEh = *(const uint4*)(g_eBh + so);
        pEl = *(const uint4*)(g_eBl + so);
    }
    for (int sweep = 0; sweep < 14; ++sweep) {
        if (sweep == 0) {
#pragma unroll
            for (int s = 0; s < 4; ++s)
                layer1A<2>(s_obs, 2 * s, prop_W1 + p * 576 + s * 64,
                           prop_b1 + p * 288 + s * 32, s, smc, tid);
        } else if (sweep == 2) {
#pragma unroll
            for (int s = 0; s < 4; ++s)
                layer1A<2>(s_obs, 2 * (4 + s), prop_W1 + p * 576 + (4 + s) * 64,
                           prop_b1 + p * 288 + (4 + s) * 32, s, smc, tid);
        } else if (sweep == 4) {
            layer1A<2>(s_obs, 16, prop_W1 + p * 576 + 512, prop_b1 + p * 288 + 256, 0, smc, tid);
            layer1A<6>(s_obs, 18, ext_W1 + p * 384, ext_b1 + p * 64, 1, smc, tid);
            layer1A<6>(s_obs, 24, ext_W1 + p * 384 + 192, ext_b1 + p * 64 + 32, 2, smc, tid);
            layer1A<18>(s_obs, 30, opp_W1 + p * 576, opp_b1 + p * 32, 3, smc, tid);
        }
        if (sweep * 4 + bslot < 54) {
            *(uint4*)(smc + stEh) = pEh;
            *(uint4*)(smc + stEl) = pEl;
        }
        __syncthreads();
        {   // prefetch next sweep's B
            int ntile = (sweep + 1) * 4 + bslot;
            if (ntile < 54) {
                long so = ((long)(p * 54 + ntile) * 32 + brr) * 32 + bu * 8;
                pEh = *(const uint4*)(g_eBh + so);
                pEl = *(const uint4*)(g_eBl + so);
            }
        }
        // gemm: warp -> m16 x n32 of one tile
        {
            int w = tid >> 5, lane = tid & 31;
            int m0 = (w & 3) * 16, slot = w >> 2;
            int tile = sweep * 4 + slot;
            if (tile < 54) {
                int asl = (tile < 16) ? ((tile >> 1) & 3)
                                      : (tile < 18 ? 0 : (tile < 27 ? 1 : (tile < 36 ? 2 : 3)));
                int ecol = (tile < 18) ? tile * 32
                          : (tile < 27 ? (tile - 18) * 32
                          : (tile < 36 ? 288 + (tile - 27) * 32 : (tile - 36) * 32));
                bool addm = tile >= 18;
                int fr = ((lane >> 3) & 1) * 8 + (lane & 7), fu = lane >> 4;
                float d[4][4];
#pragma unroll
                for (int j = 0; j < 4; ++j)
#pragma unroll
                    for (int q = 0; q < 4; ++q) d[j][q] = 0.f;
#pragma unroll
                for (int ks = 0; ks < 2; ++ks) {
                    int ua = ks * 2 + fu;
                    u32 ah[4], al[4], bh[2][4], bl[2][4];
                    ldm_x4(ah, sbase + swa(AENC_H + asl * 4096, m0 + fr, ua));
                    ldm_x4(al, sbase + swa(AENC_L + asl * 4096, m0 + fr, ua));
                    ldm_x4(bh[0], sbase + swa(BENC_H + slot * 2048, fr, ua));
                    ldm_x4(bh[1], sbase + swa(BENC_H + slot * 2048, 16 + fr, ua));
                    ldm_x4(bl[0], sbase + swa(BENC_L + slot * 2048, fr, ua));
                    ldm_x4(bl[1], sbase + swa(BENC_L + slot * 2048, 16 + fr, ua));
#pragma unroll
                    for (int nt = 0; nt < 4; ++nt) {
                        int nh = nt >> 1, hf = nt & 1;
                        mma16816(d[nt], ah, bh[nh][hf], bh[nh][2 + hf]);
                        mma16816(d[nt], ah, bl[nh][hf], bl[nh][2 + hf]);
                        mma16816(d[nt], al, bh[nh][hf], bh[nh][2 + hf]);
                    }
                }
#pragma unroll
                for (int nt = 0; nt < 4; ++nt) {
                    int col = ecol + nt * 8 + (lane & 3) * 2;
                    int r0 = m0 + (lane >> 2);
                    float2 b = *(const float2*)(bias_sm + tile * 32 + nt * 8 + (lane & 3) * 2);
                    float2 v0 = make_float2(lrelu(d[nt][0] + b.x), lrelu(d[nt][1] + b.y));
                    float2 v1 = make_float2(lrelu(d[nt][2] + b.x), lrelu(d[nt][3] + b.y));
                    float* e0 = s_enc + r0 * ENC_LD + col;
                    float* e1 = e0 + 8 * ENC_LD;
                    if (addm) {
                        float2 o0 = *(float2*)e0, o1 = *(float2*)e1;
                        v0.x += o0.x; v0.y += o0.y; v1.x += o1.x; v1.y += o1.y;
                    }
                    *(float2*)e0 = v0;
                    *(float2*)e1 = v1;
                }
            }
        }
        __syncthreads();
    }

    // ======== pi MLP ========
    // pi1: A converted from fp32 enc; OUTPUT written as h1 tiles (enc dead).
    pi_gemm<false, true>(s_enc, ENC_LD, 576, &g_B1h[p][0][0], &g_B1l[p][0][0],
                         cst, (float*)0, 0, 0, 0, H1T_H, H1T_L, smc, sbase, tid);
    // pi2: A read in place from h1 tiles; fp32 out to h2.
    pi_gemm<true, false>((const float*)0, 0, 256, &g_B2h[p][0][0], &g_B2l[p][0][0],
                         cst + 256, sm + H2_B / 4, H_LD, H1T_H, H1T_L, 0, 0,
                         smc, sbase, tid);

    if (tid < 192) {
        int row = tid / 3, o = tid - row * 3;
        const float* h2 = sm + H2_B / 4 + row * H_LD;
        float acc = cst[1280 + o];
#pragma unroll 8
        for (int k = 0; k < 256; ++k)
            acc = fmaf(h2[k], cst[512 + k * 3 + o], acc);
        out[((long)(row0 + row) * 3 + p) * 3 + o] = tanhf(acc);
    }
}

extern "C" void kernel_launch(void* const* d_in, const int* in_sizes, int n_in,
                              void* d_out, int out_size) {
    const float* obs = (const float*)d_in[0];
    const float* prop_W1 = (const float*)d_in[1];
    const float* prop_b1 = (const float*)d_in[2];
    const float* prop_W2 = (const float*)d_in[3];
    const float* prop_b2 = (const float*)d_in[4];
    const float* ext_W1 = (const float*)d_in[5];
    const float* ext_b1 = (const float*)d_in[6];
    const float* ext_W2 = (const float*)d_in[7];
    const float* ext_b2 = (const float*)d_in[8];
    const float* opp_W1 = (const float*)d_in[9];
    const float* opp_b1 = (const float*)d_in[10];
    const float* opp_W2 = (const float*)d_in[11];
    const float* opp_b2 = (const float*)d_in[12];
    const float* pi_W1 = (const float*)d_in[13];
    const float* pi_b1 = (const float*)d_in[14];
    const float* pi_W2 = (const float*)d_in[15];
    const float* pi_b2 = (const float*)d_in[16];
    const float* pi_W3 = (const float*)d_in[17];
    const float* pi_b3 = (const float*)d_in[18];
    float* out = (float*)d_out;

    prep_kernel<<<1728, 256>>>(pi_W1, pi_W2, prop_W2, ext_W2, opp_W2);

    cudaFuncSetAttribute(mlpac_kernel, cudaFuncAttributeMaxDynamicSharedMemorySize, SMEM_B);
    dim3 grid(65536 / TM, 3, 1);
    mlpac_kernel<<<grid, NT, SMEM_B>>>(
        obs, prop_W1, prop_b1, prop_W2, prop_b2, ext_W1, ext_b1, ext_W2, ext_b2,
        opp_W1, opp_b1, opp_W2, opp_b2, pi_W1, pi_b1, pi_W2, pi_b2, pi_W3, pi_b3,
        out);
}